// round 6
// baseline (speedup 1.0000x reference)
#include <cuda_runtime.h>
#include <cuda_bf16.h>
#include <cstdint>

#define BATCH 4
#define SQ    1024
#define HID   4096
#define NH    32
#define NKV   8
#define HD    128
#define KVLEN 2048
#define TOKS  (BATCH*SQ)

// ---------------- scratch (device globals; allocation-free) ----------------
__device__ float g_qlin[(size_t)TOKS*HID];
__device__ float g_klin[(size_t)TOKS*NKV*HD];
__device__ float g_vlin[(size_t)TOKS*NKV*HD];
__device__ float g_kc[(size_t)BATCH*NKV*KVLEN*HD];
__device__ float g_vc[(size_t)BATCH*NKV*KVLEN*HD];
__device__ float g_attn[(size_t)TOKS*HID];
__device__ float g_scores[(size_t)BATCH*NH*SQ*KVLEN];   // 1 GiB

// ---------------- tf32 helpers ----------------
__device__ __forceinline__ float to_tf32(float x) {
    uint32_t u;
    asm("cvt.rna.tf32.f32 %0, %1;" : "=r"(u) : "f"(x));
    return __uint_as_float(u);
}

__device__ __forceinline__ void mma8(float* d,
                                     float a0, float a1, float a2, float a3,
                                     float b0, float b1) {
    asm volatile(
        "mma.sync.aligned.m16n8k8.row.col.f32.tf32.tf32.f32 "
        "{%0,%1,%2,%3}, {%4,%5,%6,%7}, {%8,%9}, {%0,%1,%2,%3};\n"
        : "+f"(d[0]), "+f"(d[1]), "+f"(d[2]), "+f"(d[3])
        : "r"(__float_as_uint(a0)), "r"(__float_as_uint(a1)),
          "r"(__float_as_uint(a2)), "r"(__float_as_uint(a3)),
          "r"(__float_as_uint(b0)), "r"(__float_as_uint(b1)));
}

// Core 128x128x16 block-tile compute, 3xTF32 split (hh + hl + lh).
// A smem: [row][k] pad 20. B smem indexed via (n*BN + k*BK).
// Warp grid 2(m) x 4(n); warp tile 64x32; mma grid 4x4.
template<int BN, int BK>
__device__ __forceinline__ void mma_block(
    const float* __restrict__ Ah, const float* __restrict__ Al,
    const float* __restrict__ Bh, const float* __restrict__ Bl,
    int wm, int wn, int g, int t, float acc[4][4][4])
{
#pragma unroll
    for (int ks = 0; ks < 16; ks += 8) {
        float ah[4][4], al[4][4];
#pragma unroll
        for (int mt = 0; mt < 4; ++mt) {
            const int r0 = (wm + mt*16 + g)*20 + ks + t;
            const int r1 = r0 + 8*20;
            ah[mt][0] = Ah[r0]; ah[mt][1] = Ah[r1];
            ah[mt][2] = Ah[r0+4]; ah[mt][3] = Ah[r1+4];
            al[mt][0] = Al[r0]; al[mt][1] = Al[r1];
            al[mt][2] = Al[r0+4]; al[mt][3] = Al[r1+4];
        }
#pragma unroll
        for (int nt = 0; nt < 4; ++nt) {
            const int nb = (wn + nt*8 + g)*BN;
            const float b0 = Bh[nb + (ks+t)*BK];
            const float b1 = Bh[nb + (ks+t+4)*BK];
            const float l0 = Bl[nb + (ks+t)*BK];
            const float l1 = Bl[nb + (ks+t+4)*BK];
#pragma unroll
            for (int mt = 0; mt < 4; ++mt) {
                mma8(acc[mt][nt], ah[mt][0],ah[mt][1],ah[mt][2],ah[mt][3], b0, b1);
                mma8(acc[mt][nt], ah[mt][0],ah[mt][1],ah[mt][2],ah[mt][3], l0, l1);
                mma8(acc[mt][nt], al[mt][0],al[mt][1],al[mt][2],al[mt][3], b0, b1);
            }
        }
    }
}

__device__ __forceinline__ void split_store(float* Sh, float* Sl, int idx, float4 v) {
    const float h0 = to_tf32(v.x), h1 = to_tf32(v.y),
                h2 = to_tf32(v.z), h3 = to_tf32(v.w);
    *reinterpret_cast<float4*>(Sh + idx) = make_float4(h0, h1, h2, h3);
    *reinterpret_cast<float4*>(Sl + idx) = make_float4(
        to_tf32(v.x - h0), to_tf32(v.y - h1), to_tf32(v.z - h2), to_tf32(v.w - h3));
}

// ---------------------------------------------------------------------------
// Projection / O GEMM:  C[M,N] = A[M,K] * B[N,K]^T + bias  (nn.Linear)
// ---------------------------------------------------------------------------
__global__ __launch_bounds__(256)
void gemm_proj(const float* __restrict__ A, const float* __restrict__ B,
               const float* __restrict__ bias, float* __restrict__ C,
               int N, int K)
{
    __shared__ float Ah[128*20], Al[128*20], Bh[128*20], Bl[128*20];
    const int tid = threadIdx.x;
    const int warp = tid >> 5, lane = tid & 31, g = lane >> 2, t = lane & 3;
    const int wm = (warp >> 2)*64, wn = (warp & 3)*32;
    const size_t m0 = (size_t)blockIdx.y*128, n0 = (size_t)blockIdx.x*128;
    const float* Ag = A + m0*K;
    const float* Bg = B + n0*K;
    const int lr = tid >> 2, lc = (tid & 3)*4;

    float acc[4][4][4] = {};
    float4 va[2], vb[2];
    const int KT = K >> 4;

    va[0] = *reinterpret_cast<const float4*>(Ag + (size_t)lr*K + lc);
    va[1] = *reinterpret_cast<const float4*>(Ag + (size_t)(lr+64)*K + lc);
    vb[0] = *reinterpret_cast<const float4*>(Bg + (size_t)lr*K + lc);
    vb[1] = *reinterpret_cast<const float4*>(Bg + (size_t)(lr+64)*K + lc);

    for (int kt = 0; kt < KT; ++kt) {
        split_store(Ah, Al, lr*20 + lc, va[0]);
        split_store(Ah, Al, (lr+64)*20 + lc, va[1]);
        split_store(Bh, Bl, lr*20 + lc, vb[0]);
        split_store(Bh, Bl, (lr+64)*20 + lc, vb[1]);
        __syncthreads();
        if (kt + 1 < KT) {
            const size_t off = (size_t)(kt+1)*16 + lc;
            va[0] = *reinterpret_cast<const float4*>(Ag + (size_t)lr*K + off);
            va[1] = *reinterpret_cast<const float4*>(Ag + (size_t)(lr+64)*K + off);
            vb[0] = *reinterpret_cast<const float4*>(Bg + (size_t)lr*K + off);
            vb[1] = *reinterpret_cast<const float4*>(Bg + (size_t)(lr+64)*K + off);
        }
        mma_block<20,1>(Ah, Al, Bh, Bl, wm, wn, g, t, acc);
        __syncthreads();
    }

#pragma unroll
    for (int mt = 0; mt < 4; ++mt) {
        const size_t r0 = m0 + wm + mt*16 + g, r1 = r0 + 8;
#pragma unroll
        for (int nt = 0; nt < 4; ++nt) {
            const int col = (int)n0 + wn + nt*8 + t*2;
            const float b0 = bias[col], b1 = bias[col+1];
            C[r0*N + col]   = acc[mt][nt][0] + b0;
            C[r0*N + col+1] = acc[mt][nt][1] + b1;
            C[r1*N + col]   = acc[mt][nt][2] + b0;
            C[r1*N + col+1] = acc[mt][nt][3] + b1;
        }
    }
}

// ---------------------------------------------------------------------------
// KV cache concat pack
// ---------------------------------------------------------------------------
__global__ __launch_bounds__(256)
void pack_kv(const float* __restrict__ pk, const float* __restrict__ pv,
             const float* __restrict__ kl, const float* __restrict__ vl,
             float* __restrict__ kc, float* __restrict__ vc)
{
    const size_t idx = (size_t)blockIdx.x*256 + threadIdx.x;   // float4 id
    const int d4 = (int)(idx & 31);
    const int s  = (int)((idx >> 5) & 2047);
    const int hh = (int)((idx >> 16) & 7);
    const int bb = (int)(idx >> 19);
    float4 kv, vv;
    if (s < 1024) {
        const size_t src = (((size_t)bb*NKV + hh)*1024 + s)*HD + d4*4;
        kv = *reinterpret_cast<const float4*>(pk + src);
        vv = *reinterpret_cast<const float4*>(pv + src);
    } else {
        const size_t src = ((size_t)bb*SQ + (s - 1024))*(NKV*HD) + hh*HD + d4*4;
        kv = *reinterpret_cast<const float4*>(kl + src);
        vv = *reinterpret_cast<const float4*>(vl + src);
    }
    const size_t dst = (((size_t)bb*NKV + hh)*KVLEN + s)*HD + d4*4;
    *reinterpret_cast<float4*>(kc + dst) = kv;
    *reinterpret_cast<float4*>(vc + dst) = vv;
}

// ---------------------------------------------------------------------------
// Batched QK^T: S[b,h][q][kv] = scale * Q[b,h] . K[b,h/4]^T  (+mask -> -1e9)
// grid (KVLEN/128, SQ/128, B*NH)
// ---------------------------------------------------------------------------
__global__ __launch_bounds__(256)
void qk_gemm(const float* __restrict__ Q, const float* __restrict__ Kc,
             const int* __restrict__ amask, float* __restrict__ S)
{
    __shared__ float Ah[128*20], Al[128*20], Bh[128*20], Bl[128*20];
    const int tid = threadIdx.x;
    const int warp = tid >> 5, lane = tid & 31, g = lane >> 2, t = lane & 3;
    const int wm = (warp >> 2)*64, wn = (warp & 3)*32;
    const int z = blockIdx.z, b = z >> 5, h = z & 31;
    const size_t m0 = (size_t)blockIdx.y*128, n0 = (size_t)blockIdx.x*128;
    const float* Ag = Q + ((size_t)b*SQ + m0)*HID + h*HD;
    const float* Bg = Kc + (((size_t)b*NKV + (h >> 2))*KVLEN + n0)*HD;
    const int lr = tid >> 2, lc = (tid & 3)*4;
    const float scale = 0.08838834764831843f;   // 1/sqrt(128)

    float acc[4][4][4] = {};
    float4 va[2], vb[2];

    va[0] = *reinterpret_cast<const float4*>(Ag + (size_t)lr*HID + lc);
    va[1] = *reinterpret_cast<const float4*>(Ag + (size_t)(lr+64)*HID + lc);
    vb[0] = *reinterpret_cast<const float4*>(Bg + (size_t)lr*HD + lc);
    vb[1] = *reinterpret_cast<const float4*>(Bg + (size_t)(lr+64)*HD + lc);

    for (int kt = 0; kt < 8; ++kt) {            // K = 128
        split_store(Ah, Al, lr*20 + lc, va[0]);
        split_store(Ah, Al, (lr+64)*20 + lc, va[1]);
        split_store(Bh, Bl, lr*20 + lc, vb[0]);
        split_store(Bh, Bl, (lr+64)*20 + lc, vb[1]);
        __syncthreads();
        if (kt + 1 < 8) {
            const size_t off = (size_t)(kt+1)*16 + lc;
            va[0] = *reinterpret_cast<const float4*>(Ag + (size_t)lr*HID + off);
            va[1] = *reinterpret_cast<const float4*>(Ag + (size_t)(lr+64)*HID + off);
            vb[0] = *reinterpret_cast<const float4*>(Bg + (size_t)lr*HD + off);
            vb[1] = *reinterpret_cast<const float4*>(Bg + (size_t)(lr+64)*HD + off);
        }
        mma_block<20,1>(Ah, Al, Bh, Bl, wm, wn, g, t, acc);
        __syncthreads();
    }

    float* Sb = S + (size_t)z*SQ*KVLEN;
#pragma unroll
    for (int mt = 0; mt < 4; ++mt) {
        const size_t r0 = m0 + wm + mt*16 + g, r1 = r0 + 8;
#pragma unroll
        for (int nt = 0; nt < 4; ++nt) {
            const int col = (int)n0 + wn + nt*8 + t*2;
            const bool mk0 = amask[(size_t)b*KVLEN + col] != 0;
            const bool mk1 = amask[(size_t)b*KVLEN + col + 1] != 0;
            Sb[r0*KVLEN + col]   = mk0 ? -1e9f : acc[mt][nt][0]*scale;
            Sb[r0*KVLEN + col+1] = mk1 ? -1e9f : acc[mt][nt][1]*scale;
            Sb[r1*KVLEN + col]   = mk0 ? -1e9f : acc[mt][nt][2]*scale;
            Sb[r1*KVLEN + col+1] = mk1 ? -1e9f : acc[mt][nt][3]*scale;
        }
    }
}

// ---------------------------------------------------------------------------
// Row softmax over KVLEN=2048, in place. grid = B*NH*SQ, 256 threads.
// ---------------------------------------------------------------------------
__global__ __launch_bounds__(256)
void softmax_rows(float* __restrict__ S)
{
    float* p = S + (size_t)blockIdx.x*KVLEN;
    const int tid = threadIdx.x;
    float4 a = *reinterpret_cast<float4*>(p + tid*4);
    float4 c = *reinterpret_cast<float4*>(p + 1024 + tid*4);
    float x[8] = {a.x, a.y, a.z, a.w, c.x, c.y, c.z, c.w};

    float m = x[0];
#pragma unroll
    for (int i = 1; i < 8; ++i) m = fmaxf(m, x[i]);
#pragma unroll
    for (int o = 16; o; o >>= 1) m = fmaxf(m, __shfl_xor_sync(0xffffffffu, m, o));
    __shared__ float red[8];
    if ((tid & 31) == 0) red[tid >> 5] = m;
    __syncthreads();
    float M = red[0];
#pragma unroll
    for (int i = 1; i < 8; ++i) M = fmaxf(M, red[i]);
    __syncthreads();

    float s = 0.f;
#pragma unroll
    for (int i = 0; i < 8; ++i) { x[i] = __expf(x[i] - M); s += x[i]; }
#pragma unroll
    for (int o = 16; o; o >>= 1) s += __shfl_xor_sync(0xffffffffu, s, o);
    if ((tid & 31) == 0) red[tid >> 5] = s;
    __syncthreads();
    float T = 0.f;
#pragma unroll
    for (int i = 0; i < 8; ++i) T += red[i];
    const float r = 1.f / T;

    *reinterpret_cast<float4*>(p + tid*4) =
        make_float4(x[0]*r, x[1]*r, x[2]*r, x[3]*r);
    *reinterpret_cast<float4*>(p + 1024 + tid*4) =
        make_float4(x[4]*r, x[5]*r, x[6]*r, x[7]*r);
}

// ---------------------------------------------------------------------------
// Batched PV: O[b,h][q][d] = P[b,h] . V[b,h/4]   (P [Sq,KV] k-contig,
// V [KV,128] n-contig). Writes g_attn in [tok][h*128+d] layout.
// grid (1, SQ/128, B*NH)
// ---------------------------------------------------------------------------
__global__ __launch_bounds__(256)
void pv_gemm(const float* __restrict__ P, const float* __restrict__ V,
             float* __restrict__ O)
{
    __shared__ float Ph[128*20], Pl[128*20], Vh[16*132], Vl[16*132];
    const int tid = threadIdx.x;
    const int warp = tid >> 5, lane = tid & 31, g = lane >> 2, t = lane & 3;
    const int wm = (warp >> 2)*64, wn = (warp & 3)*32;
    const int z = blockIdx.z, b = z >> 5, h = z & 31;
    const size_t m0 = (size_t)blockIdx.y*128;
    const float* Ag = P + ((size_t)z*SQ + m0)*KVLEN;
    const float* Bg = V + ((size_t)b*NKV + (h >> 2))*KVLEN*HD;
    const int ar = tid >> 2, ac = (tid & 3)*4;       // A rows 0..63 (+64)
    const int br = tid >> 5, bc = (tid & 31)*4;      // B k-rows 0..7 (+8)

    float acc[4][4][4] = {};
    float4 va[2], vb[2];

    va[0] = *reinterpret_cast<const float4*>(Ag + (size_t)ar*KVLEN + ac);
    va[1] = *reinterpret_cast<const float4*>(Ag + (size_t)(ar+64)*KVLEN + ac);
    vb[0] = *reinterpret_cast<const float4*>(Bg + (size_t)br*HD + bc);
    vb[1] = *reinterpret_cast<const float4*>(Bg + (size_t)(br+8)*HD + bc);

    for (int kt = 0; kt < KVLEN/16; ++kt) {
        split_store(Ph, Pl, ar*20 + ac, va[0]);
        split_store(Ph, Pl, (ar+64)*20 + ac, va[1]);
        split_store(Vh, Vl, br*132 + bc, vb[0]);
        split_store(Vh, Vl, (br+8)*132 + bc, vb[1]);
        __syncthreads();
        if (kt + 1 < KVLEN/16) {
            const size_t ko = (size_t)(kt+1)*16;
            va[0] = *reinterpret_cast<const float4*>(Ag + (size_t)ar*KVLEN + ko + ac);
            va[1] = *reinterpret_cast<const float4*>(Ag + (size_t)(ar+64)*KVLEN + ko + ac);
            vb[0] = *reinterpret_cast<const float4*>(Bg + (ko + br)*HD + bc);
            vb[1] = *reinterpret_cast<const float4*>(Bg + (ko + br + 8)*HD + bc);
        }
        mma_block<1,132>(Ph, Pl, Vh, Vl, wm, wn, g, t, acc);
        __syncthreads();
    }

#pragma unroll
    for (int mt = 0; mt < 4; ++mt) {
        const size_t r0 = (size_t)b*SQ + m0 + wm + mt*16 + g, r1 = r0 + 8;
#pragma unroll
        for (int nt = 0; nt < 4; ++nt) {
            const int col = h*HD + wn + nt*8 + t*2;
            O[r0*HID + col]   = acc[mt][nt][0];
            O[r0*HID + col+1] = acc[mt][nt][1];
            O[r1*HID + col]   = acc[mt][nt][2];
            O[r1*HID + col+1] = acc[mt][nt][3];
        }
    }
}

// ---------------------------------------------------------------------------
extern "C" void kernel_launch(void* const* d_in, const int* in_sizes, int n_in,
                              void* d_out, int out_size)
{
    (void)in_sizes; (void)n_in; (void)out_size;
    const float* hs = (const float*)d_in[0];
    const float* pk = (const float*)d_in[1];
    const float* pv = (const float*)d_in[2];
    const int*   am = (const int*)  d_in[3];
    const float* Wq = (const float*)d_in[4];
    const float* bq = (const float*)d_in[5];
    const float* Wk = (const float*)d_in[6];
    const float* bk = (const float*)d_in[7];
    const float* Wv = (const float*)d_in[8];
    const float* bv = (const float*)d_in[9];
    const float* Wo = (const float*)d_in[10];
    const float* bo = (const float*)d_in[11];
    float* out = (float*)d_out;

    float *qlin, *klin, *vlin, *kc, *vc, *attn, *sc;
    cudaGetSymbolAddress((void**)&qlin, g_qlin);
    cudaGetSymbolAddress((void**)&klin, g_klin);
    cudaGetSymbolAddress((void**)&vlin, g_vlin);
    cudaGetSymbolAddress((void**)&kc,   g_kc);
    cudaGetSymbolAddress((void**)&vc,   g_vc);
    cudaGetSymbolAddress((void**)&attn, g_attn);
    cudaGetSymbolAddress((void**)&sc,   g_scores);

    gemm_proj<<<dim3(HID/128, TOKS/128), 256>>>(hs, Wq, bq, qlin, HID, HID);
    gemm_proj<<<dim3((NKV*HD)/128, TOKS/128), 256>>>(hs, Wk, bk, klin, NKV*HD, HID);
    gemm_proj<<<dim3((NKV*HD)/128, TOKS/128), 256>>>(hs, Wv, bv, vlin, NKV*HD, HID);
    pack_kv<<<(BATCH*NKV*KVLEN*32)/256, 256>>>(pk, pv, klin, vlin, kc, vc);
    qk_gemm<<<dim3(KVLEN/128, SQ/128, BATCH*NH), 256>>>(qlin, kc, am, sc);
    softmax_rows<<<BATCH*NH*SQ, 256>>>(sc);
    pv_gemm<<<dim3(1, SQ/128, BATCH*NH), 256>>>(sc, vc, attn);
    gemm_proj<<<dim3(HID/128, TOKS/128), 256>>>(attn, Wo, bo, out, HID, HID);
}

// round 9
// speedup vs baseline: 1.3623x; 1.3623x over previous
#include <cuda_runtime.h>
#include <cuda_bf16.h>
#include <cstdint>

#define BATCH 4
#define SQ    1024
#define HID   4096
#define NH    32
#define NKV   8
#define HD    128
#define KVLEN 2048
#define TOKS  (BATCH*SQ)

// ---------------- scratch (device globals; allocation-free) ----------------
__device__ float g_qlin[(size_t)TOKS*HID];
__device__ float g_klin[(size_t)TOKS*NKV*HD];
__device__ float g_vlin[(size_t)TOKS*NKV*HD];
__device__ float g_kc[(size_t)BATCH*NKV*KVLEN*HD];
__device__ float g_vc[(size_t)BATCH*NKV*KVLEN*HD];
__device__ float g_attn[(size_t)TOKS*HID];
__device__ float g_scores[(size_t)BATCH*NH*SQ*KVLEN];   // 1 GiB

// ---------------- bf16 split helpers ----------------
__device__ __forceinline__ uint32_t bfpack(__nv_bfloat16 a, __nv_bfloat16 b) {
    uint16_t ua = *reinterpret_cast<uint16_t*>(&a);
    uint16_t ub = *reinterpret_cast<uint16_t*>(&b);
    return (uint32_t)ua | ((uint32_t)ub << 16);
}

// (x0,x1) -> uint2{ hi-pair, lo-pair }  (low half = x0 = even k)
__device__ __forceinline__ uint2 splitpair(float x0, float x1) {
    __nv_bfloat16 h0 = __float2bfloat16(x0);
    __nv_bfloat16 h1 = __float2bfloat16(x1);
    __nv_bfloat16 l0 = __float2bfloat16(x0 - __bfloat162float(h0));
    __nv_bfloat16 l1 = __float2bfloat16(x1 - __bfloat162float(h1));
    uint2 o; o.x = bfpack(h0, h1); o.y = bfpack(l0, l1);
    return o;
}

// float4 (4 consecutive k) -> two consecutive uint2 smem elements as uint4
__device__ __forceinline__ uint4 split4(float4 v) {
    uint2 p0 = splitpair(v.x, v.y);
    uint2 p1 = splitpair(v.z, v.w);
    return make_uint4(p0.x, p0.y, p1.x, p1.y);
}

__device__ __forceinline__ void mma16(float* d,
                                      uint32_t a0, uint32_t a1, uint32_t a2, uint32_t a3,
                                      uint32_t b0, uint32_t b1) {
    asm volatile(
        "mma.sync.aligned.m16n8k16.row.col.f32.bf16.bf16.f32 "
        "{%0,%1,%2,%3}, {%4,%5,%6,%7}, {%8,%9}, {%0,%1,%2,%3};\n"
        : "+f"(d[0]), "+f"(d[1]), "+f"(d[2]), "+f"(d[3])
        : "r"(a0), "r"(a1), "r"(a2), "r"(a3), "r"(b0), "r"(b1));
}

// ---------------------------------------------------------------------------
// Tile helpers: 128 rows x 32 k  ->  smem uint2[128][20] (16 k-pairs + pad 4).
// Loader: row = tid>>3 (+32j), c = tid&7 -> LDG.128 fully coalesced,
// STS.128 tiles all 32 banks. Frag LDS.64: bank start (8g+2t) -> conflict-free.
// ---------------------------------------------------------------------------
#define TSTRIDE 20

__device__ __forceinline__ void load_tile_regs(const float* __restrict__ g, size_t ld,
                                               int tid, float4 f[4]) {
    const int row = tid >> 3, c = (tid & 7) * 4;
#pragma unroll
    for (int j = 0; j < 4; ++j)
        f[j] = *reinterpret_cast<const float4*>(g + (size_t)(row + 32*j)*ld + c);
}

__device__ __forceinline__ void store_tile(uint2* __restrict__ S, int tid,
                                           const float4 f[4]) {
    const int row = tid >> 3, c = (tid & 7) * 2;
#pragma unroll
    for (int j = 0; j < 4; ++j)
        *reinterpret_cast<uint4*>(&S[(row + 32*j)*TSTRIDE + c]) = split4(f[j]);
}

// 128x128x32 block compute: warp grid 2(m) x 4(n), warp tile 64x32, mma 4x4.
// 3 passes: hi*hi + hi*lo + lo*hi.
__device__ __forceinline__ void mma_block(const uint2* __restrict__ As,
                                          const uint2* __restrict__ Bs,
                                          int wm, int wn, int g, int t,
                                          float acc[4][4][4])
{
#pragma unroll
    for (int s = 0; s < 2; ++s) {
        uint2 af[4][4];
#pragma unroll
        for (int mt = 0; mt < 4; ++mt) {
            const int r0 = (wm + mt*16 + g)*TSTRIDE + s*8 + t;
            af[mt][0] = As[r0];
            af[mt][1] = As[r0 + 8*TSTRIDE];
            af[mt][2] = As[r0 + 4];
            af[mt][3] = As[r0 + 8*TSTRIDE + 4];
        }
        uint2 bf[4][2];
#pragma unroll
        for (int nt = 0; nt < 4; ++nt) {
            const int rb = (wn + nt*8 + g)*TSTRIDE + s*8 + t;
            bf[nt][0] = Bs[rb];
            bf[nt][1] = Bs[rb + 4];
        }
#pragma unroll
        for (int mt = 0; mt < 4; ++mt)
#pragma unroll
            for (int nt = 0; nt < 4; ++nt) {
                mma16(acc[mt][nt], af[mt][0].x, af[mt][1].x, af[mt][2].x, af[mt][3].x,
                      bf[nt][0].x, bf[nt][1].x);
                mma16(acc[mt][nt], af[mt][0].x, af[mt][1].x, af[mt][2].x, af[mt][3].x,
                      bf[nt][0].y, bf[nt][1].y);
                mma16(acc[mt][nt], af[mt][0].y, af[mt][1].y, af[mt][2].y, af[mt][3].y,
                      bf[nt][0].x, bf[nt][1].x);
            }
    }
}

// ---------------------------------------------------------------------------
// Projection / O GEMM:  C[M,N] = A[M,K] * B[N,K]^T + bias  (nn.Linear)
// grid (N/128, M/128), 256 threads
// ---------------------------------------------------------------------------
__global__ __launch_bounds__(256)
void gemm_proj(const float* __restrict__ A, const float* __restrict__ B,
               const float* __restrict__ bias, float* __restrict__ C,
               int N, int K)
{
    __shared__ uint2 As[128*TSTRIDE], Bs[128*TSTRIDE];
    const int tid = threadIdx.x;
    const int warp = tid >> 5, lane = tid & 31, g = lane >> 2, t = lane & 3;
    const int wm = (warp >> 2)*64, wn = (warp & 3)*32;
    const size_t m0 = (size_t)blockIdx.y*128, n0 = (size_t)blockIdx.x*128;
    const float* Ag = A + m0*K;
    const float* Bg = B + n0*K;

    float acc[4][4][4] = {};
    float4 fa[4], fb[4];
    const int KT = K >> 5;

    load_tile_regs(Ag, K, tid, fa);
    load_tile_regs(Bg, K, tid, fb);

    for (int kt = 0; kt < KT; ++kt) {
        store_tile(As, tid, fa);
        store_tile(Bs, tid, fb);
        __syncthreads();
        if (kt + 1 < KT) {
            load_tile_regs(Ag + (size_t)(kt+1)*32, K, tid, fa);
            load_tile_regs(Bg + (size_t)(kt+1)*32, K, tid, fb);
        }
        mma_block(As, Bs, wm, wn, g, t, acc);
        __syncthreads();
    }

#pragma unroll
    for (int mt = 0; mt < 4; ++mt) {
        const size_t r0 = m0 + wm + mt*16 + g, r1 = r0 + 8;
#pragma unroll
        for (int nt = 0; nt < 4; ++nt) {
            const int col = (int)n0 + wn + nt*8 + t*2;
            const float b0 = bias[col], b1 = bias[col+1];
            C[r0*N + col]   = acc[mt][nt][0] + b0;
            C[r0*N + col+1] = acc[mt][nt][1] + b1;
            C[r1*N + col]   = acc[mt][nt][2] + b0;
            C[r1*N + col+1] = acc[mt][nt][3] + b1;
        }
    }
}

// ---------------------------------------------------------------------------
// KV cache concat pack
// ---------------------------------------------------------------------------
__global__ __launch_bounds__(256)
void pack_kv(const float* __restrict__ pk, const float* __restrict__ pv,
             const float* __restrict__ kl, const float* __restrict__ vl,
             float* __restrict__ kc, float* __restrict__ vc)
{
    const size_t idx = (size_t)blockIdx.x*256 + threadIdx.x;   // float4 id
    const int d4 = (int)(idx & 31);
    const int s  = (int)((idx >> 5) & 2047);
    const int hh = (int)((idx >> 16) & 7);
    const int bb = (int)(idx >> 19);
    float4 kv, vv;
    if (s < 1024) {
        const size_t src = (((size_t)bb*NKV + hh)*1024 + s)*HD + d4*4;
        kv = *reinterpret_cast<const float4*>(pk + src);
        vv = *reinterpret_cast<const float4*>(pv + src);
    } else {
        const size_t src = ((size_t)bb*SQ + (s - 1024))*(NKV*HD) + hh*HD + d4*4;
        kv = *reinterpret_cast<const float4*>(kl + src);
        vv = *reinterpret_cast<const float4*>(vl + src);
    }
    const size_t dst = (((size_t)bb*NKV + hh)*KVLEN + s)*HD + d4*4;
    *reinterpret_cast<float4*>(kc + dst) = kv;
    *reinterpret_cast<float4*>(vc + dst) = vv;
}

// ---------------------------------------------------------------------------
// Batched QK^T: S = scale * Q.K^T (+mask). grid (KVLEN/128, SQ/128, B*NH)
// ---------------------------------------------------------------------------
__global__ __launch_bounds__(256)
void qk_gemm(const float* __restrict__ Q, const float* __restrict__ Kc,
             const int* __restrict__ amask, float* __restrict__ S)
{
    __shared__ uint2 As[128*TSTRIDE], Bs[128*TSTRIDE];
    const int tid = threadIdx.x;
    const int warp = tid >> 5, lane = tid & 31, g = lane >> 2, t = lane & 3;
    const int wm = (warp >> 2)*64, wn = (warp & 3)*32;
    const int z = blockIdx.z, b = z >> 5, h = z & 31;
    const size_t m0 = (size_t)blockIdx.y*128, n0 = (size_t)blockIdx.x*128;
    const float* Ag = Q + ((size_t)b*SQ + m0)*HID + h*HD;
    const float* Bg = Kc + (((size_t)b*NKV + (h >> 2))*KVLEN + n0)*HD;
    const float scale = 0.08838834764831843f;   // 1/sqrt(128)

    float acc[4][4][4] = {};
    float4 fa[4], fb[4];

    load_tile_regs(Ag, HID, tid, fa);
    load_tile_regs(Bg, HD, tid, fb);

    for (int kt = 0; kt < 4; ++kt) {            // K = 128
        store_tile(As, tid, fa);
        store_tile(Bs, tid, fb);
        __syncthreads();
        if (kt + 1 < 4) {
            load_tile_regs(Ag + (size_t)(kt+1)*32, HID, tid, fa);
            load_tile_regs(Bg + (size_t)(kt+1)*32, HD, tid, fb);
        }
        mma_block(As, Bs, wm, wn, g, t, acc);
        __syncthreads();
    }

    float* Sb = S + (size_t)z*SQ*KVLEN;
#pragma unroll
    for (int mt = 0; mt < 4; ++mt) {
        const size_t r0 = m0 + wm + mt*16 + g, r1 = r0 + 8;
#pragma unroll
        for (int nt = 0; nt < 4; ++nt) {
            const int col = (int)n0 + wn + nt*8 + t*2;
            const bool mk0 = amask[(size_t)b*KVLEN + col] != 0;
            const bool mk1 = amask[(size_t)b*KVLEN + col + 1] != 0;
            Sb[r0*KVLEN + col]   = mk0 ? -1e9f : acc[mt][nt][0]*scale;
            Sb[r0*KVLEN + col+1] = mk1 ? -1e9f : acc[mt][nt][1]*scale;
            Sb[r1*KVLEN + col]   = mk0 ? -1e9f : acc[mt][nt][2]*scale;
            Sb[r1*KVLEN + col+1] = mk1 ? -1e9f : acc[mt][nt][3]*scale;
        }
    }
}

// ---------------------------------------------------------------------------
// Row softmax over KVLEN=2048, in place. grid = B*NH*SQ, 256 threads.
// ---------------------------------------------------------------------------
__global__ __launch_bounds__(256)
void softmax_rows(float* __restrict__ S)
{
    float* p = S + (size_t)blockIdx.x*KVLEN;
    const int tid = threadIdx.x;
    float4 a = *reinterpret_cast<float4*>(p + tid*4);
    float4 c = *reinterpret_cast<float4*>(p + 1024 + tid*4);
    float x[8] = {a.x, a.y, a.z, a.w, c.x, c.y, c.z, c.w};

    float m = x[0];
#pragma unroll
    for (int i = 1; i < 8; ++i) m = fmaxf(m, x[i]);
#pragma unroll
    for (int o = 16; o; o >>= 1) m = fmaxf(m, __shfl_xor_sync(0xffffffffu, m, o));
    __shared__ float red[8];
    if ((tid & 31) == 0) red[tid >> 5] = m;
    __syncthreads();
    float M = red[0];
#pragma unroll
    for (int i = 1; i < 8; ++i) M = fmaxf(M, red[i]);
    __syncthreads();

    float s = 0.f;
#pragma unroll
    for (int i = 0; i < 8; ++i) { x[i] = __expf(x[i] - M); s += x[i]; }
#pragma unroll
    for (int o = 16; o; o >>= 1) s += __shfl_xor_sync(0xffffffffu, s, o);
    if ((tid & 31) == 0) red[tid >> 5] = s;
    __syncthreads();
    float T = 0.f;
#pragma unroll
    for (int i = 0; i < 8; ++i) T += red[i];
    const float r = 1.f / T;

    *reinterpret_cast<float4*>(p + tid*4) =
        make_float4(x[0]*r, x[1]*r, x[2]*r, x[3]*r);
    *reinterpret_cast<float4*>(p + 1024 + tid*4) =
        make_float4(x[4]*r, x[5]*r, x[6]*r, x[7]*r);
}

// ---------------------------------------------------------------------------
// Batched PV: O[q][h*128+d] = P . V.  P [Sq,KV] k-contig, V [KV,128] n-contig
// (transposed while staging to smem). grid (1, SQ/128, B*NH)
// ---------------------------------------------------------------------------
__global__ __launch_bounds__(256)
void pv_gemm(const float* __restrict__ P, const float* __restrict__ V,
             float* __restrict__ O)
{
    __shared__ uint2 As[128*TSTRIDE], Bs[128*TSTRIDE];
    const int tid = threadIdx.x;
    const int warp = tid >> 5, lane = tid & 31, g = lane >> 2, t = lane & 3;
    const int wm = (warp >> 2)*64, wn = (warp & 3)*32;
    const int z = blockIdx.z, b = z >> 5, h = z & 31;
    const size_t m0 = (size_t)blockIdx.y*128;
    const float* Ag = P + ((size_t)z*SQ + m0)*KVLEN;
    const float* Vg = V + ((size_t)b*NKV + (h >> 2))*KVLEN*HD;

    const int kp = tid & 15, nh0 = tid >> 4;   // V transpose mapping

    float acc[4][4][4] = {};
    float4 fa[4], fv[2][2];

    auto load_v = [&](int kt) {
        const float* Vt = Vg + (size_t)kt*32*HD;
#pragma unroll
        for (int j = 0; j < 2; ++j) {
            const int nq = nh0 + 16*j;
            fv[j][0] = *reinterpret_cast<const float4*>(Vt + (size_t)(2*kp)*HD + nq*4);
            fv[j][1] = *reinterpret_cast<const float4*>(Vt + (size_t)(2*kp+1)*HD + nq*4);
        }
    };
    auto store_v = [&]() {
#pragma unroll
        for (int j = 0; j < 2; ++j) {
            const int n0 = (nh0 + 16*j)*4;
            Bs[(n0+0)*TSTRIDE + kp] = splitpair(fv[j][0].x, fv[j][1].x);
            Bs[(n0+1)*TSTRIDE + kp] = splitpair(fv[j][0].y, fv[j][1].y);
            Bs[(n0+2)*TSTRIDE + kp] = splitpair(fv[j][0].z, fv[j][1].z);
            Bs[(n0+3)*TSTRIDE + kp] = splitpair(fv[j][0].w, fv[j][1].w);
        }
    };

    load_tile_regs(Ag, KVLEN, tid, fa);
    load_v(0);

    for (int kt = 0; kt < KVLEN/32; ++kt) {
        store_tile(As, tid, fa);
        store_v();
        __syncthreads();
        if (kt + 1 < KVLEN/32) {
            load_tile_regs(Ag + (size_t)(kt+1)*32, KVLEN, tid, fa);
            load_v(kt + 1);
        }
        mma_block(As, Bs, wm, wn, g, t, acc);
        __syncthreads();
    }

#pragma unroll
    for (int mt = 0; mt < 4; ++mt) {
        const size_t r0 = (size_t)b*SQ + m0 + wm + mt*16 + g, r1 = r0 + 8;
#pragma unroll
        for (int nt = 0; nt < 4; ++nt) {
            const int col = h*HD + wn + nt*8 + t*2;
            O[r0*HID + col]   = acc[mt][nt][0];
            O[r0*HID + col+1] = acc[mt][nt][1];
            O[r1*HID + col]   = acc[mt][nt][2];
            O[r1*HID + col+1] = acc[mt][nt][3];
        }
    }
}

// ---------------------------------------------------------------------------
extern "C" void kernel_launch(void* const* d_in, const int* in_sizes, int n_in,
                              void* d_out, int out_size)
{
    (void)in_sizes; (void)n_in; (void)out_size;
    const float* hs = (const float*)d_in[0];
    const float* pk = (const float*)d_in[1];
    const float* pv = (const float*)d_in[2];
    const int*   am = (const int*)  d_in[3];
    const float* Wq = (const float*)d_in[4];
    const float* bq = (const float*)d_in[5];
    const float* Wk = (const float*)d_in[6];
    const float* bk = (const float*)d_in[7];
    const float* Wv = (const float*)d_in[8];
    const float* bv = (const float*)d_in[9];
    const float* Wo = (const float*)d_in[10];
    const float* bo = (const float*)d_in[11];
    float* out = (float*)d_out;

    float *qlin, *klin, *vlin, *kc, *vc, *attn, *sc;
    cudaGetSymbolAddress((void**)&qlin, g_qlin);
    cudaGetSymbolAddress((void**)&klin, g_klin);
    cudaGetSymbolAddress((void**)&vlin, g_vlin);
    cudaGetSymbolAddress((void**)&kc,   g_kc);
    cudaGetSymbolAddress((void**)&vc,   g_vc);
    cudaGetSymbolAddress((void**)&attn, g_attn);
    cudaGetSymbolAddress((void**)&sc,   g_scores);

    gemm_proj<<<dim3(HID/128, TOKS/128), 256>>>(hs, Wq, bq, qlin, HID, HID);
    gemm_proj<<<dim3((NKV*HD)/128, TOKS/128), 256>>>(hs, Wk, bk, klin, NKV*HD, HID);
    gemm_proj<<<dim3((NKV*HD)/128, TOKS/128), 256>>>(hs, Wv, bv, vlin, NKV*HD, HID);
    pack_kv<<<(BATCH*NKV*KVLEN*32)/256, 256>>>(pk, pv, klin, vlin, kc, vc);
    qk_gemm<<<dim3(KVLEN/128, SQ/128, BATCH*NH), 256>>>(qlin, kc, am, sc);
    softmax_rows<<<BATCH*NH*SQ, 256>>>(sc);
    pv_gemm<<<dim3(1, SQ/128, BATCH*NH), 256>>>(sc, vc, attn);
    gemm_proj<<<dim3(HID/128, TOKS/128), 256>>>(attn, Wo, bo, out, HID, HID);
}

// round 10
// speedup vs baseline: 1.6138x; 1.1846x over previous
#include <cuda_runtime.h>
#include <cuda_bf16.h>
#include <cstdint>

#define BATCH 4
#define SQ    1024
#define HID   4096
#define NH    32
#define NKV   8
#define HD    128
#define KVLEN 2048
#define TOKS  (BATCH*SQ)

// ---------------- scratch (device globals; allocation-free) ----------------
// packed split format: uint2 { bf16x2 hi(k,k+1), bf16x2 lo(k,k+1) }  per k-pair
__device__ uint2 g_hs_s[(size_t)TOKS*HID/2];         // hidden_states split
__device__ uint2 g_wq_s[(size_t)HID*HID/2];
__device__ uint2 g_wk_s[(size_t)NKV*HD*HID/2];
__device__ uint2 g_wv_s[(size_t)NKV*HD*HID/2];
__device__ uint2 g_wo_s[(size_t)HID*HID/2];
__device__ uint2 g_qs [(size_t)TOKS*HID/2];          // Q proj, split
__device__ float g_klin[(size_t)TOKS*NKV*HD];
__device__ float g_vlin[(size_t)TOKS*NKV*HD];
__device__ uint2 g_kcs[(size_t)BATCH*NKV*KVLEN*HD/2];// K cache, split
__device__ float g_vc [(size_t)BATCH*NKV*KVLEN*HD];  // V cache, f32
__device__ uint2 g_as [(size_t)TOKS*HID/2];          // attn out, split
__device__ float g_scores[(size_t)BATCH*NH*SQ*KVLEN];// 1 GiB (f32 -> split in place)

// ---------------- bf16 split helpers ----------------
__device__ __forceinline__ uint32_t bfpack(__nv_bfloat16 a, __nv_bfloat16 b) {
    uint16_t ua = *reinterpret_cast<uint16_t*>(&a);
    uint16_t ub = *reinterpret_cast<uint16_t*>(&b);
    return (uint32_t)ua | ((uint32_t)ub << 16);
}

__device__ __forceinline__ uint2 splitpair(float x0, float x1) {
    __nv_bfloat16 h0 = __float2bfloat16(x0);
    __nv_bfloat16 h1 = __float2bfloat16(x1);
    __nv_bfloat16 l0 = __float2bfloat16(x0 - __bfloat162float(h0));
    __nv_bfloat16 l1 = __float2bfloat16(x1 - __bfloat162float(h1));
    uint2 o; o.x = bfpack(h0, h1); o.y = bfpack(l0, l1);
    return o;
}

__device__ __forceinline__ uint4 split4(float4 v) {
    uint2 p0 = splitpair(v.x, v.y);
    uint2 p1 = splitpair(v.z, v.w);
    return make_uint4(p0.x, p0.y, p1.x, p1.y);
}

__device__ __forceinline__ void mma16(float* d,
                                      uint32_t a0, uint32_t a1, uint32_t a2, uint32_t a3,
                                      uint32_t b0, uint32_t b1) {
    asm volatile(
        "mma.sync.aligned.m16n8k16.row.col.f32.bf16.bf16.f32 "
        "{%0,%1,%2,%3}, {%4,%5,%6,%7}, {%8,%9}, {%0,%1,%2,%3};\n"
        : "+f"(d[0]), "+f"(d[1]), "+f"(d[2]), "+f"(d[3])
        : "r"(a0), "r"(a1), "r"(a2), "r"(a3), "r"(b0), "r"(b1));
}

// ---------------------------------------------------------------------------
// Pre-split kernel: f32 array -> packed split uint2 (same byte size).
// ---------------------------------------------------------------------------
__global__ __launch_bounds__(256)
void split_f32(const float* __restrict__ in, uint2* __restrict__ out, size_t n4)
{
    const size_t i = (size_t)blockIdx.x*256 + threadIdx.x;   // float4 index
    if (i >= n4) return;
    float4 v = reinterpret_cast<const float4*>(in)[i];
    reinterpret_cast<uint4*>(out)[i] = split4(v);
}

// ---------------------------------------------------------------------------
// Tile: 128 rows x 32 k = 16 k-pairs/row -> smem uint2[128][20] (pad 4).
// Loader: row=tid>>3 (+32j), c=(tid&7)*2 uint2 -> LDG.128 coalesced,
// STS.128 bank-tiling. Frag LDS.64 conflict-free (bank start 8g+2t).
// ---------------------------------------------------------------------------
#define TSTRIDE 20

__device__ __forceinline__ void load_tile_u(const uint2* __restrict__ g, size_t ld,
                                            int tid, uint4 f[4]) {
    const int row = tid >> 3, c = (tid & 7) * 2;
#pragma unroll
    for (int j = 0; j < 4; ++j)
        f[j] = *reinterpret_cast<const uint4*>(g + (size_t)(row + 32*j)*ld + c);
}

__device__ __forceinline__ void store_tile_u(uint2* __restrict__ S, int tid,
                                             const uint4 f[4]) {
    const int row = tid >> 3, c = (tid & 7) * 2;
#pragma unroll
    for (int j = 0; j < 4; ++j)
        *reinterpret_cast<uint4*>(&S[(row + 32*j)*TSTRIDE + c]) = f[j];
}

// 128x128x32 block compute: warp grid 2(m) x 4(n), warp tile 64x32, mma 4x4.
// 3 passes: hi*hi + hi*lo + lo*hi.
__device__ __forceinline__ void mma_block(const uint2* __restrict__ As,
                                          const uint2* __restrict__ Bs,
                                          int wm, int wn, int g, int t,
                                          float acc[4][4][4])
{
#pragma unroll
    for (int s = 0; s < 2; ++s) {
        uint2 af[4][4];
#pragma unroll
        for (int mt = 0; mt < 4; ++mt) {
            const int r0 = (wm + mt*16 + g)*TSTRIDE + s*8 + t;
            af[mt][0] = As[r0];
            af[mt][1] = As[r0 + 8*TSTRIDE];
            af[mt][2] = As[r0 + 4];
            af[mt][3] = As[r0 + 8*TSTRIDE + 4];
        }
        uint2 bf[4][2];
#pragma unroll
        for (int nt = 0; nt < 4; ++nt) {
            const int rb = (wn + nt*8 + g)*TSTRIDE + s*8 + t;
            bf[nt][0] = Bs[rb];
            bf[nt][1] = Bs[rb + 4];
        }
#pragma unroll
        for (int mt = 0; mt < 4; ++mt)
#pragma unroll
            for (int nt = 0; nt < 4; ++nt) {
                mma16(acc[mt][nt], af[mt][0].x, af[mt][1].x, af[mt][2].x, af[mt][3].x,
                      bf[nt][0].x, bf[nt][1].x);
                mma16(acc[mt][nt], af[mt][0].x, af[mt][1].x, af[mt][2].x, af[mt][3].x,
                      bf[nt][0].y, bf[nt][1].y);
                mma16(acc[mt][nt], af[mt][0].y, af[mt][1].y, af[mt][2].y, af[mt][3].y,
                      bf[nt][0].x, bf[nt][1].x);
            }
    }
}

// ---------------------------------------------------------------------------
// GEMM on pre-split operands: C[M,N] = A[M,K].B[N,K]^T + bias.
// SPLIT_OUT: write C as packed split uint2 [M][N/2] instead of f32.
// grid (N/128, M/128), 256 threads.
// ---------------------------------------------------------------------------
template<bool SPLIT_OUT>
__global__ __launch_bounds__(256)
void gemm_s(const uint2* __restrict__ A, const uint2* __restrict__ B,
            const float* __restrict__ bias, void* __restrict__ Cv,
            int N, int K)
{
    __shared__ uint2 As[128*TSTRIDE], Bs[128*TSTRIDE];
    const int tid = threadIdx.x;
    const int warp = tid >> 5, lane = tid & 31, g = lane >> 2, t = lane & 3;
    const int wm = (warp >> 2)*64, wn = (warp & 3)*32;
    const size_t m0 = (size_t)blockIdx.y*128, n0 = (size_t)blockIdx.x*128;
    const size_t lda = (size_t)K >> 1;
    const uint2* Ag = A + m0*lda;
    const uint2* Bg = B + n0*lda;

    float acc[4][4][4] = {};
    uint4 fa[4], fb[4];
    const int KT = K >> 5;

    load_tile_u(Ag, lda, tid, fa);
    load_tile_u(Bg, lda, tid, fb);

    for (int kt = 0; kt < KT; ++kt) {
        store_tile_u(As, tid, fa);
        store_tile_u(Bs, tid, fb);
        __syncthreads();
        if (kt + 1 < KT) {
            load_tile_u(Ag + (size_t)(kt+1)*16, lda, tid, fa);
            load_tile_u(Bg + (size_t)(kt+1)*16, lda, tid, fb);
        }
        mma_block(As, Bs, wm, wn, g, t, acc);
        __syncthreads();
    }

#pragma unroll
    for (int mt = 0; mt < 4; ++mt) {
        const size_t r0 = m0 + wm + mt*16 + g, r1 = r0 + 8;
#pragma unroll
        for (int nt = 0; nt < 4; ++nt) {
            const int col = (int)n0 + wn + nt*8 + t*2;
            const float b0 = bias[col], b1 = bias[col+1];
            if (SPLIT_OUT) {
                uint2* C = reinterpret_cast<uint2*>(Cv);
                const size_t ldc = (size_t)N >> 1;
                C[r0*ldc + (col>>1)] = splitpair(acc[mt][nt][0]+b0, acc[mt][nt][1]+b1);
                C[r1*ldc + (col>>1)] = splitpair(acc[mt][nt][2]+b0, acc[mt][nt][3]+b1);
            } else {
                float* C = reinterpret_cast<float*>(Cv);
                C[r0*N + col]   = acc[mt][nt][0] + b0;
                C[r0*N + col+1] = acc[mt][nt][1] + b1;
                C[r1*N + col]   = acc[mt][nt][2] + b0;
                C[r1*N + col+1] = acc[mt][nt][3] + b1;
            }
        }
    }
}

// ---------------------------------------------------------------------------
// KV cache concat pack: K cache -> split uint2, V cache -> f32.
// ---------------------------------------------------------------------------
__global__ __launch_bounds__(256)
void pack_kv_s(const float* __restrict__ pk, const float* __restrict__ pv,
               const float* __restrict__ kl, const float* __restrict__ vl,
               uint2* __restrict__ kcs, float* __restrict__ vc)
{
    const size_t idx = (size_t)blockIdx.x*256 + threadIdx.x;   // float4 id
    const int d4 = (int)(idx & 31);
    const int s  = (int)((idx >> 5) & 2047);
    const int hh = (int)((idx >> 16) & 7);
    const int bb = (int)(idx >> 19);
    float4 kv, vv;
    if (s < 1024) {
        const size_t src = (((size_t)bb*NKV + hh)*1024 + s)*HD + d4*4;
        kv = *reinterpret_cast<const float4*>(pk + src);
        vv = *reinterpret_cast<const float4*>(pv + src);
    } else {
        const size_t src = ((size_t)bb*SQ + (s - 1024))*(NKV*HD) + hh*HD + d4*4;
        kv = *reinterpret_cast<const float4*>(kl + src);
        vv = *reinterpret_cast<const float4*>(vl + src);
    }
    const size_t row = ((size_t)bb*NKV + hh)*KVLEN + s;
    *reinterpret_cast<uint4*>(kcs + row*(HD/2) + d4*2) = split4(kv);
    *reinterpret_cast<float4*>(vc + row*HD + d4*4) = vv;
}

// ---------------------------------------------------------------------------
// Batched QK^T on pre-split Q and K-cache. grid (KVLEN/128, SQ/128, B*NH)
// ---------------------------------------------------------------------------
__global__ __launch_bounds__(256)
void qk_gemm_s(const uint2* __restrict__ Q, const uint2* __restrict__ Kcs,
               const int* __restrict__ amask, float* __restrict__ S)
{
    __shared__ uint2 As[128*TSTRIDE], Bs[128*TSTRIDE];
    const int tid = threadIdx.x;
    const int warp = tid >> 5, lane = tid & 31, g = lane >> 2, t = lane & 3;
    const int wm = (warp >> 2)*64, wn = (warp & 3)*32;
    const int z = blockIdx.z, b = z >> 5, h = z & 31;
    const size_t m0 = (size_t)blockIdx.y*128, n0 = (size_t)blockIdx.x*128;
    const uint2* Ag = Q + ((size_t)b*SQ + m0)*(HID/2) + h*(HD/2);
    const uint2* Bg = Kcs + (((size_t)b*NKV + (h >> 2))*KVLEN + n0)*(HD/2);
    const float scale = 0.08838834764831843f;   // 1/sqrt(128)

    float acc[4][4][4] = {};
    uint4 fa[4], fb[4];

    load_tile_u(Ag, HID/2, tid, fa);
    load_tile_u(Bg, HD/2, tid, fb);

    for (int kt = 0; kt < 4; ++kt) {            // K = 128
        store_tile_u(As, tid, fa);
        store_tile_u(Bs, tid, fb);
        __syncthreads();
        if (kt + 1 < 4) {
            load_tile_u(Ag + (size_t)(kt+1)*16, HID/2, tid, fa);
            load_tile_u(Bg + (size_t)(kt+1)*16, HD/2, tid, fb);
        }
        mma_block(As, Bs, wm, wn, g, t, acc);
        __syncthreads();
    }

    float* Sb = S + (size_t)z*SQ*KVLEN;
#pragma unroll
    for (int mt = 0; mt < 4; ++mt) {
        const size_t r0 = m0 + wm + mt*16 + g, r1 = r0 + 8;
#pragma unroll
        for (int nt = 0; nt < 4; ++nt) {
            const int col = (int)n0 + wn + nt*8 + t*2;
            const bool mk0 = amask[(size_t)b*KVLEN + col] != 0;
            const bool mk1 = amask[(size_t)b*KVLEN + col + 1] != 0;
            Sb[r0*KVLEN + col]   = mk0 ? -1e9f : acc[mt][nt][0]*scale;
            Sb[r0*KVLEN + col+1] = mk1 ? -1e9f : acc[mt][nt][1]*scale;
            Sb[r1*KVLEN + col]   = mk0 ? -1e9f : acc[mt][nt][2]*scale;
            Sb[r1*KVLEN + col+1] = mk1 ? -1e9f : acc[mt][nt][3]*scale;
        }
    }
}

// ---------------------------------------------------------------------------
// Row softmax over KVLEN=2048, writes packed split IN PLACE (same bytes).
// grid = B*NH*SQ, 256 threads.
// ---------------------------------------------------------------------------
__global__ __launch_bounds__(256)
void softmax_rows_s(float* __restrict__ S)
{
    float* p = S + (size_t)blockIdx.x*KVLEN;
    const int tid = threadIdx.x;
    float4 a = *reinterpret_cast<float4*>(p + tid*4);
    float4 c = *reinterpret_cast<float4*>(p + 1024 + tid*4);
    float x[8] = {a.x, a.y, a.z, a.w, c.x, c.y, c.z, c.w};

    float m = x[0];
#pragma unroll
    for (int i = 1; i < 8; ++i) m = fmaxf(m, x[i]);
#pragma unroll
    for (int o = 16; o; o >>= 1) m = fmaxf(m, __shfl_xor_sync(0xffffffffu, m, o));
    __shared__ float red[8];
    if ((tid & 31) == 0) red[tid >> 5] = m;
    __syncthreads();
    float M = red[0];
#pragma unroll
    for (int i = 1; i < 8; ++i) M = fmaxf(M, red[i]);
    __syncthreads();

    float s = 0.f;
#pragma unroll
    for (int i = 0; i < 8; ++i) { x[i] = __expf(x[i] - M); s += x[i]; }
#pragma unroll
    for (int o = 16; o; o >>= 1) s += __shfl_xor_sync(0xffffffffu, s, o);
    if ((tid & 31) == 0) red[tid >> 5] = s;
    __syncthreads();
    float T = 0.f;
#pragma unroll
    for (int i = 0; i < 8; ++i) T += red[i];
    const float r = 1.f / T;

    uint2* ps = reinterpret_cast<uint2*>(p);
    *reinterpret_cast<uint4*>(&ps[tid*2]) =
        split4(make_float4(x[0]*r, x[1]*r, x[2]*r, x[3]*r));
    *reinterpret_cast<uint4*>(&ps[512 + tid*2]) =
        split4(make_float4(x[4]*r, x[5]*r, x[6]*r, x[7]*r));
}

// ---------------------------------------------------------------------------
// Batched PV on pre-split P; V transposed+split while staging.
// Writes attn split [tok][ (h*128+d)/2 ]. grid (1, SQ/128, B*NH)
// ---------------------------------------------------------------------------
__global__ __launch_bounds__(256)
void pv_gemm_s(const uint2* __restrict__ P, const float* __restrict__ V,
               uint2* __restrict__ O)
{
    __shared__ uint2 As[128*TSTRIDE], Bs[128*TSTRIDE];
    const int tid = threadIdx.x;
    const int warp = tid >> 5, lane = tid & 31, g = lane >> 2, t = lane & 3;
    const int wm = (warp >> 2)*64, wn = (warp & 3)*32;
    const int z = blockIdx.z, b = z >> 5, h = z & 31;
    const size_t m0 = (size_t)blockIdx.y*128;
    const uint2* Ag = P + ((size_t)z*SQ + m0)*(KVLEN/2);
    const float* Vg = V + ((size_t)b*NKV + (h >> 2))*KVLEN*HD;

    const int kp = tid & 15, nh0 = tid >> 4;   // V transpose mapping

    float acc[4][4][4] = {};
    uint4 fa[4];
    float4 fv[2][2];

    auto load_v = [&](int kt) {
        const float* Vt = Vg + (size_t)kt*32*HD;
#pragma unroll
        for (int j = 0; j < 2; ++j) {
            const int nq = nh0 + 16*j;
            fv[j][0] = *reinterpret_cast<const float4*>(Vt + (size_t)(2*kp)*HD + nq*4);
            fv[j][1] = *reinterpret_cast<const float4*>(Vt + (size_t)(2*kp+1)*HD + nq*4);
        }
    };
    auto store_v = [&]() {
#pragma unroll
        for (int j = 0; j < 2; ++j) {
            const int n0 = (nh0 + 16*j)*4;
            Bs[(n0+0)*TSTRIDE + kp] = splitpair(fv[j][0].x, fv[j][1].x);
            Bs[(n0+1)*TSTRIDE + kp] = splitpair(fv[j][0].y, fv[j][1].y);
            Bs[(n0+2)*TSTRIDE + kp] = splitpair(fv[j][0].z, fv[j][1].z);
            Bs[(n0+3)*TSTRIDE + kp] = splitpair(fv[j][0].w, fv[j][1].w);
        }
    };

    load_tile_u(Ag, KVLEN/2, tid, fa);
    load_v(0);

    for (int kt = 0; kt < KVLEN/32; ++kt) {
        store_tile_u(As, tid, fa);
        store_v();
        __syncthreads();
        if (kt + 1 < KVLEN/32) {
            load_tile_u(Ag + (size_t)(kt+1)*16, KVLEN/2, tid, fa);
            load_v(kt + 1);
        }
        mma_block(As, Bs, wm, wn, g, t, acc);
        __syncthreads();
    }

#pragma unroll
    for (int mt = 0; mt < 4; ++mt) {
        const size_t r0 = (size_t)b*SQ + m0 + wm + mt*16 + g, r1 = r0 + 8;
#pragma unroll
        for (int nt = 0; nt < 4; ++nt) {
            const int col = h*HD + wn + nt*8 + t*2;
            O[r0*(HID/2) + (col>>1)] = splitpair(acc[mt][nt][0], acc[mt][nt][1]);
            O[r1*(HID/2) + (col>>1)] = splitpair(acc[mt][nt][2], acc[mt][nt][3]);
        }
    }
}

// ---------------------------------------------------------------------------
extern "C" void kernel_launch(void* const* d_in, const int* in_sizes, int n_in,
                              void* d_out, int out_size)
{
    (void)in_sizes; (void)n_in; (void)out_size;
    const float* hs = (const float*)d_in[0];
    const float* pk = (const float*)d_in[1];
    const float* pv = (const float*)d_in[2];
    const int*   am = (const int*)  d_in[3];
    const float* Wq = (const float*)d_in[4];
    const float* bq = (const float*)d_in[5];
    const float* Wk = (const float*)d_in[6];
    const float* bk = (const float*)d_in[7];
    const float* Wv = (const float*)d_in[8];
    const float* bv = (const float*)d_in[9];
    const float* Wo = (const float*)d_in[10];
    const float* bo = (const float*)d_in[11];
    float* out = (float*)d_out;

    uint2 *hs_s, *wq_s, *wk_s, *wv_s, *wo_s, *qs, *kcs, *as;
    float *klin, *vlin, *vc, *sc;
    cudaGetSymbolAddress((void**)&hs_s, g_hs_s);
    cudaGetSymbolAddress((void**)&wq_s, g_wq_s);
    cudaGetSymbolAddress((void**)&wk_s, g_wk_s);
    cudaGetSymbolAddress((void**)&wv_s, g_wv_s);
    cudaGetSymbolAddress((void**)&wo_s, g_wo_s);
    cudaGetSymbolAddress((void**)&qs,   g_qs);
    cudaGetSymbolAddress((void**)&kcs,  g_kcs);
    cudaGetSymbolAddress((void**)&as,   g_as);
    cudaGetSymbolAddress((void**)&klin, g_klin);
    cudaGetSymbolAddress((void**)&vlin, g_vlin);
    cudaGetSymbolAddress((void**)&vc,   g_vc);
    cudaGetSymbolAddress((void**)&sc,   g_scores);

    // pre-split inputs (memory-bound, one pass each)
    const size_t n4_hs = (size_t)TOKS*HID/4;
    const size_t n4_wq = (size_t)HID*HID/4;
    const size_t n4_wk = (size_t)NKV*HD*HID/4;
    split_f32<<<(unsigned)((n4_hs+255)/256), 256>>>(hs, hs_s, n4_hs);
    split_f32<<<(unsigned)((n4_wq+255)/256), 256>>>(Wq, wq_s, n4_wq);
    split_f32<<<(unsigned)((n4_wk+255)/256), 256>>>(Wk, wk_s, n4_wk);
    split_f32<<<(unsigned)((n4_wk+255)/256), 256>>>(Wv, wv_s, n4_wk);
    split_f32<<<(unsigned)((n4_wq+255)/256), 256>>>(Wo, wo_s, n4_wq);

    // projections
    gemm_s<true ><<<dim3(HID/128, TOKS/128), 256>>>(hs_s, wq_s, bq, qs,   HID,     HID);
    gemm_s<false><<<dim3((NKV*HD)/128, TOKS/128), 256>>>(hs_s, wk_s, bk, klin, NKV*HD, HID);
    gemm_s<false><<<dim3((NKV*HD)/128, TOKS/128), 256>>>(hs_s, wv_s, bv, vlin, NKV*HD, HID);

    // KV cache concat (K -> split, V -> f32)
    pack_kv_s<<<(BATCH*NKV*KVLEN*32)/256, 256>>>(pk, pv, klin, vlin, kcs, vc);

    // attention
    qk_gemm_s<<<dim3(KVLEN/128, SQ/128, BATCH*NH), 256>>>(qs, kcs, am, sc);
    softmax_rows_s<<<BATCH*NH*SQ, 256>>>(sc);
    pv_gemm_s<<<dim3(1, SQ/128, BATCH*NH), 256>>>((const uint2*)sc, vc, as);

    // output projection
    gemm_s<false><<<dim3(HID/128, TOKS/128), 256>>>(as, wo_s, bo, out, HID, HID);
}

// round 15
// speedup vs baseline: 2.2966x; 1.4231x over previous
#include <cuda_runtime.h>
#include <cuda_fp16.h>
#include <cstdint>

#define BATCH 4
#define SQ    1024
#define HID   4096
#define NH    32
#define NKV   8
#define HD    128
#define KVLEN 2048
#define TOKS  (BATCH*SQ)

// ---------------- scratch (device globals; allocation-free) ----------------
// packed split format: uint2 { fp16x2 hi(k,k+1), fp16x2 lo(k,k+1) } per k-pair
__device__ uint2 g_hs_s[(size_t)TOKS*HID/2];
__device__ uint2 g_wq_s[(size_t)HID*HID/2];
__device__ uint2 g_wk_s[(size_t)NKV*HD*HID/2];
__device__ uint2 g_wv_s[(size_t)NKV*HD*HID/2];
__device__ uint2 g_wo_s[(size_t)HID*HID/2];
__device__ uint2 g_qs [(size_t)TOKS*HID/2];
__device__ float g_klin[(size_t)TOKS*NKV*HD];
__device__ float g_vlin[(size_t)TOKS*NKV*HD];
__device__ uint2 g_kcs[(size_t)BATCH*NKV*KVLEN*HD/2];
__device__ float g_vc [(size_t)BATCH*NKV*KVLEN*HD];
__device__ uint2 g_as [(size_t)TOKS*HID/2];
__device__ float g_scores[(size_t)BATCH*NH*SQ*KVLEN];

// ---------------- fp16 split helpers ----------------
__device__ __forceinline__ uint32_t hpack(__half a, __half b) {
    uint16_t ua = *reinterpret_cast<uint16_t*>(&a);
    uint16_t ub = *reinterpret_cast<uint16_t*>(&b);
    return (uint32_t)ua | ((uint32_t)ub << 16);
}

// (x0,x1) -> uint2{ hi-pair, lo-pair }   A = hi + lo captures x to ~2^-24
__device__ __forceinline__ uint2 splitpair(float x0, float x1) {
    __half h0 = __float2half_rn(x0);
    __half h1 = __float2half_rn(x1);
    __half l0 = __float2half_rn(x0 - __half2float(h0));
    __half l1 = __float2half_rn(x1 - __half2float(h1));
    uint2 o; o.x = hpack(h0, h1); o.y = hpack(l0, l1);
    return o;
}

__device__ __forceinline__ uint4 split4(float4 v) {
    uint2 p0 = splitpair(v.x, v.y);
    uint2 p1 = splitpair(v.z, v.w);
    return make_uint4(p0.x, p0.y, p1.x, p1.y);
}

__device__ __forceinline__ void mma16(float* d,
                                      uint32_t a0, uint32_t a1, uint32_t a2, uint32_t a3,
                                      uint32_t b0, uint32_t b1) {
    asm volatile(
        "mma.sync.aligned.m16n8k16.row.col.f32.f16.f16.f32 "
        "{%0,%1,%2,%3}, {%4,%5,%6,%7}, {%8,%9}, {%0,%1,%2,%3};\n"
        : "+f"(d[0]), "+f"(d[1]), "+f"(d[2]), "+f"(d[3])
        : "r"(a0), "r"(a1), "r"(a2), "r"(a3), "r"(b0), "r"(b1));
}

// ---------------------------------------------------------------------------
// Tile: 128 rows x 32 k = 16 k-pairs/row -> smem uint2[128][20] (pad 4).
// Loader: row=tid>>3 (+32j), c=(tid&7)*2 uint2 -> LDG.128 coalesced,
// STS.128 bank-tiling. Frag LDS.64 conflict-free (bank start 8g+2t).
// ---------------------------------------------------------------------------
#define TSTRIDE 20

__device__ __forceinline__ void load_tile_u(const uint2* __restrict__ g, size_t ld,
                                            int tid, uint4 f[4]) {
    const int row = tid >> 3, c = (tid & 7) * 2;
#pragma unroll
    for (int j = 0; j < 4; ++j)
        f[j] = *reinterpret_cast<const uint4*>(g + (size_t)(row + 32*j)*ld + c);
}

__device__ __forceinline__ void store_tile_u(uint2* __restrict__ S, int tid,
                                             const uint4 f[4]) {
    const int row = tid >> 3, c = (tid & 7) * 2;
#pragma unroll
    for (int j = 0; j < 4; ++j)
        *reinterpret_cast<uint4*>(&S[(row + 32*j)*TSTRIDE + c]) = f[j];
}

// 128x128x32 block compute: warp grid 2(m) x 4(n), warp tile 64x32, mma 4x4.
// fp16 2-pass: Ah*Bh + Al*Bh  (= A . fp16(B))
__device__ __forceinline__ void mma_block(const uint2* __restrict__ As,
                                          const uint2* __restrict__ Bs,
                                          int wm, int wn, int g, int t,
                                          float acc[4][4][4])
{
#pragma unroll
    for (int s = 0; s < 2; ++s) {
        uint2 af[4][4];
#pragma unroll
        for (int mt = 0; mt < 4; ++mt) {
            const int r0 = (wm + mt*16 + g)*TSTRIDE + s*8 + t;
            af[mt][0] = As[r0];
            af[mt][1] = As[r0 + 8*TSTRIDE];
            af[mt][2] = As[r0 + 4];
            af[mt][3] = As[r0 + 8*TSTRIDE + 4];
        }
        uint32_t bf[4][2];
#pragma unroll
        for (int nt = 0; nt < 4; ++nt) {
            const int rb = (wn + nt*8 + g)*TSTRIDE + s*8 + t;
            bf[nt][0] = Bs[rb].x;
            bf[nt][1] = Bs[rb + 4].x;
        }
#pragma unroll
        for (int mt = 0; mt < 4; ++mt)
#pragma unroll
            for (int nt = 0; nt < 4; ++nt) {
                mma16(acc[mt][nt], af[mt][0].x, af[mt][1].x, af[mt][2].x, af[mt][3].x,
                      bf[nt][0], bf[nt][1]);
                mma16(acc[mt][nt], af[mt][0].y, af[mt][1].y, af[mt][2].y, af[mt][3].y,
                      bf[nt][0], bf[nt][1]);
            }
    }
}

// ---------------------------------------------------------------------------
// GEMM on pre-split operands: C[M,N] = A[M,K].B[N,K]^T + bias.
// SPLIT_OUT: write C as packed split uint2 [M][N/2] instead of f32.
// grid (N/128, M/128), 256 threads.
// ---------------------------------------------------------------------------
template<bool SPLIT_OUT>
__global__ __launch_bounds__(256)
void gemm_s(const uint2* __restrict__ A, const uint2* __restrict__ B,
            const float* __restrict__ bias, void* __restrict__ Cv,
            int N, int K)
{
    __shared__ uint2 As[128*TSTRIDE], Bs[128*TSTRIDE];
    const int tid = threadIdx.x;
    const int warp = tid >> 5, lane = tid & 31, g = lane >> 2, t = lane & 3;
    const int wm = (warp >> 2)*64, wn = (warp & 3)*32;
    const size_t m0 = (size_t)blockIdx.y*128, n0 = (size_t)blockIdx.x*128;
    const size_t lda = (size_t)K >> 1;
    const uint2* Ag = A + m0*lda;
    const uint2* Bg = B + n0*lda;

    float acc[4][4][4] = {};
    uint4 fa[4], fb[4];
    const int KT = K >> 5;

    load_tile_u(Ag, lda, tid, fa);
    load_tile_u(Bg, lda, tid, fb);

    for (int kt = 0; kt < KT; ++kt) {
        store_tile_u(As, tid, fa);
        store_tile_u(Bs, tid, fb);
        __syncthreads();
        if (kt + 1 < KT) {
            load_tile_u(Ag + (size_t)(kt+1)*16, lda, tid, fa);
            load_tile_u(Bg + (size_t)(kt+1)*16, lda, tid, fb);
        }
        mma_block(As, Bs, wm, wn, g, t, acc);
        __syncthreads();
    }

#pragma unroll
    for (int mt = 0; mt < 4; ++mt) {
        const size_t r0 = m0 + wm + mt*16 + g, r1 = r0 + 8;
#pragma unroll
        for (int nt = 0; nt < 4; ++nt) {
            const int col = (int)n0 + wn + nt*8 + t*2;
            const float b0 = bias[col], b1 = bias[col+1];
            if (SPLIT_OUT) {
                uint2* C = reinterpret_cast<uint2*>(Cv);
                const size_t ldc = (size_t)N >> 1;
                C[r0*ldc + (col>>1)] = splitpair(acc[mt][nt][0]+b0, acc[mt][nt][1]+b1);
                C[r1*ldc + (col>>1)] = splitpair(acc[mt][nt][2]+b0, acc[mt][nt][3]+b1);
            } else {
                float* C = reinterpret_cast<float*>(Cv);
                C[r0*N + col]   = acc[mt][nt][0] + b0;
                C[r0*N + col+1] = acc[mt][nt][1] + b1;
                C[r1*N + col]   = acc[mt][nt][2] + b0;
                C[r1*N + col+1] = acc[mt][nt][3] + b1;
            }
        }
    }
}

// ---------------------------------------------------------------------------
// Pre-split kernel: f32 array -> packed split uint2 (same byte size).
// ---------------------------------------------------------------------------
__global__ __launch_bounds__(256)
void split_f32(const float* __restrict__ in, uint2* __restrict__ out, size_t n4)
{
    const size_t i = (size_t)blockIdx.x*256 + threadIdx.x;
    if (i >= n4) return;
    float4 v = reinterpret_cast<const float4*>(in)[i];
    reinterpret_cast<uint4*>(out)[i] = split4(v);
}

// ---------------------------------------------------------------------------
// KV cache concat pack: K cache -> split uint2, V cache -> f32.
// ---------------------------------------------------------------------------
__global__ __launch_bounds__(256)
void pack_kv_s(const float* __restrict__ pk, const float* __restrict__ pv,
               const float* __restrict__ kl, const float* __restrict__ vl,
               uint2* __restrict__ kcs, float* __restrict__ vc)
{
    const size_t idx = (size_t)blockIdx.x*256 + threadIdx.x;
    const int d4 = (int)(idx & 31);
    const int s  = (int)((idx >> 5) & 2047);
    const int hh = (int)((idx >> 16) & 7);
    const int bb = (int)(idx >> 19);
    float4 kv, vv;
    if (s < 1024) {
        const size_t src = (((size_t)bb*NKV + hh)*1024 + s)*HD + d4*4;
        kv = *reinterpret_cast<const float4*>(pk + src);
        vv = *reinterpret_cast<const float4*>(pv + src);
    } else {
        const size_t src = ((size_t)bb*SQ + (s - 1024))*(NKV*HD) + hh*HD + d4*4;
        kv = *reinterpret_cast<const float4*>(kl + src);
        vv = *reinterpret_cast<const float4*>(vl + src);
    }
    const size_t row = ((size_t)bb*NKV + hh)*KVLEN + s;
    *reinterpret_cast<uint4*>(kcs + row*(HD/2) + d4*2) = split4(kv);
    *reinterpret_cast<float4*>(vc + row*HD + d4*4) = vv;
}

// ---------------------------------------------------------------------------
// Batched QK^T on pre-split Q and K-cache. grid (KVLEN/128, SQ/128, B*NH)
// ---------------------------------------------------------------------------
__global__ __launch_bounds__(256)
void qk_gemm_s(const uint2* __restrict__ Q, const uint2* __restrict__ Kcs,
               const int* __restrict__ amask, float* __restrict__ S)
{
    __shared__ uint2 As[128*TSTRIDE], Bs[128*TSTRIDE];
    const int tid = threadIdx.x;
    const int warp = tid >> 5, lane = tid & 31, g = lane >> 2, t = lane & 3;
    const int wm = (warp >> 2)*64, wn = (warp & 3)*32;
    const int z = blockIdx.z, b = z >> 5, h = z & 31;
    const size_t m0 = (size_t)blockIdx.y*128, n0 = (size_t)blockIdx.x*128;
    const uint2* Ag = Q + ((size_t)b*SQ + m0)*(HID/2) + h*(HD/2);
    const uint2* Bg = Kcs + (((size_t)b*NKV + (h >> 2))*KVLEN + n0)*(HD/2);
    const float scale = 0.08838834764831843f;   // 1/sqrt(128)

    float acc[4][4][4] = {};
    uint4 fa[4], fb[4];

    load_tile_u(Ag, HID/2, tid, fa);
    load_tile_u(Bg, HD/2, tid, fb);

    for (int kt = 0; kt < 4; ++kt) {            // K = 128
        store_tile_u(As, tid, fa);
        store_tile_u(Bs, tid, fb);
        __syncthreads();
        if (kt + 1 < 4) {
            load_tile_u(Ag + (size_t)(kt+1)*16, HID/2, tid, fa);
            load_tile_u(Bg + (size_t)(kt+1)*16, HD/2, tid, fb);
        }
        mma_block(As, Bs, wm, wn, g, t, acc);
        __syncthreads();
    }

    float* Sb = S + (size_t)z*SQ*KVLEN;
#pragma unroll
    for (int mt = 0; mt < 4; ++mt) {
        const size_t r0 = m0 + wm + mt*16 + g, r1 = r0 + 8;
#pragma unroll
        for (int nt = 0; nt < 4; ++nt) {
            const int col = (int)n0 + wn + nt*8 + t*2;
            const bool mk0 = amask[(size_t)b*KVLEN + col] != 0;
            const bool mk1 = amask[(size_t)b*KVLEN + col + 1] != 0;
            Sb[r0*KVLEN + col]   = mk0 ? -1e9f : acc[mt][nt][0]*scale;
            Sb[r0*KVLEN + col+1] = mk1 ? -1e9f : acc[mt][nt][1]*scale;
            Sb[r1*KVLEN + col]   = mk0 ? -1e9f : acc[mt][nt][2]*scale;
            Sb[r1*KVLEN + col+1] = mk1 ? -1e9f : acc[mt][nt][3]*scale;
        }
    }
}

// ---------------------------------------------------------------------------
// Row softmax over KVLEN=2048, writes packed split IN PLACE (same bytes).
// grid = B*NH*SQ, 256 threads.
// ---------------------------------------------------------------------------
__global__ __launch_bounds__(256)
void softmax_rows_s(float* __restrict__ S)
{
    float* p = S + (size_t)blockIdx.x*KVLEN;
    const int tid = threadIdx.x;
    float4 a = *reinterpret_cast<float4*>(p + tid*4);
    float4 c = *reinterpret_cast<float4*>(p + 1024 + tid*4);
    float x[8] = {a.x, a.y, a.z, a.w, c.x, c.y, c.z, c.w};

    float m = x[0];
#pragma unroll
    for (int i = 1; i < 8; ++i) m = fmaxf(m, x[i]);
#pragma unroll
    for (int o = 16; o; o >>= 1) m = fmaxf(m, __shfl_xor_sync(0xffffffffu, m, o));
    __shared__ float red[8];
    if ((tid & 31) == 0) red[tid >> 5] = m;
    __syncthreads();
    float M = red[0];
#pragma unroll
    for (int i = 1; i < 8; ++i) M = fmaxf(M, red[i]);
    __syncthreads();

    float s = 0.f;
#pragma unroll
    for (int i = 0; i < 8; ++i) { x[i] = __expf(x[i] - M); s += x[i]; }
#pragma unroll
    for (int o = 16; o; o >>= 1) s += __shfl_xor_sync(0xffffffffu, s, o);
    if ((tid & 31) == 0) red[tid >> 5] = s;
    __syncthreads();
    float T = 0.f;
#pragma unroll
    for (int i = 0; i < 8; ++i) T += red[i];
    const float r = 1.f / T;

    uint2* ps = reinterpret_cast<uint2*>(p);
    *reinterpret_cast<uint4*>(&ps[tid*2]) =
        split4(make_float4(x[0]*r, x[1]*r, x[2]*r, x[3]*r));
    *reinterpret_cast<uint4*>(&ps[512 + tid*2]) =
        split4(make_float4(x[4]*r, x[5]*r, x[6]*r, x[7]*r));
}

// ---------------------------------------------------------------------------
// Batched PV on pre-split P; V transposed+split while staging.
// Writes attn split [tok][(h*128+d)/2]. grid (1, SQ/128, B*NH)
// ---------------------------------------------------------------------------
__global__ __launch_bounds__(256)
void pv_gemm_s(const uint2* __restrict__ P, const float* __restrict__ V,
               uint2* __restrict__ O)
{
    __shared__ uint2 As[128*TSTRIDE], Bs[128*TSTRIDE];
    const int tid = threadIdx.x;
    const int warp = tid >> 5, lane = tid & 31, g = lane >> 2, t = lane & 3;
    const int wm = (warp >> 2)*64, wn = (warp & 3)*32;
    const int z = blockIdx.z, b = z >> 5, h = z & 31;
    const size_t m0 = (size_t)blockIdx.y*128;
    const uint2* Ag = P + ((size_t)z*SQ + m0)*(KVLEN/2);
    const float* Vg = V + ((size_t)b*NKV + (h >> 2))*KVLEN*HD;

    const int kp = tid & 15, nh0 = tid >> 4;   // V transpose mapping

    float acc[4][4][4] = {};
    uint4 fa[4];
    float4 fv[2][2];

    auto load_v = [&](int kt) {
        const float* Vt = Vg + (size_t)kt*32*HD;
#pragma unroll
        for (int j = 0; j < 2; ++j) {
            const int nq = nh0 + 16*j;
            fv[j][0] = *reinterpret_cast<const float4*>(Vt + (size_t)(2*kp)*HD + nq*4);
            fv[j][1] = *reinterpret_cast<const float4*>(Vt + (size_t)(2*kp+1)*HD + nq*4);
        }
    };
    auto store_v = [&]() {
#pragma unroll
        for (int j = 0; j < 2; ++j) {
            const int n0 = (nh0 + 16*j)*4;
            Bs[(n0+0)*TSTRIDE + kp] = splitpair(fv[j][0].x, fv[j][1].x);
            Bs[(n0+1)*TSTRIDE + kp] = splitpair(fv[j][0].y, fv[j][1].y);
            Bs[(n0+2)*TSTRIDE + kp] = splitpair(fv[j][0].z, fv[j][1].z);
            Bs[(n0+3)*TSTRIDE + kp] = splitpair(fv[j][0].w, fv[j][1].w);
        }
    };

    load_tile_u(Ag, KVLEN/2, tid, fa);
    load_v(0);

    for (int kt = 0; kt < KVLEN/32; ++kt) {
        store_tile_u(As, tid, fa);
        store_v();
        __syncthreads();
        if (kt + 1 < KVLEN/32) {
            load_tile_u(Ag + (size_t)(kt+1)*16, KVLEN/2, tid, fa);
            load_v(kt + 1);
        }
        mma_block(As, Bs, wm, wn, g, t, acc);
        __syncthreads();
    }

#pragma unroll
    for (int mt = 0; mt < 4; ++mt) {
        const size_t r0 = (size_t)b*SQ + m0 + wm + mt*16 + g, r1 = r0 + 8;
#pragma unroll
        for (int nt = 0; nt < 4; ++nt) {
            const int col = h*HD + wn + nt*8 + t*2;
            O[r0*(HID/2) + (col>>1)] = splitpair(acc[mt][nt][0], acc[mt][nt][1]);
            O[r1*(HID/2) + (col>>1)] = splitpair(acc[mt][nt][2], acc[mt][nt][3]);
        }
    }
}

// ---------------------------------------------------------------------------
extern "C" void kernel_launch(void* const* d_in, const int* in_sizes, int n_in,
                              void* d_out, int out_size)
{
    (void)in_sizes; (void)n_in; (void)out_size;
    const float* hs = (const float*)d_in[0];
    const float* pk = (const float*)d_in[1];
    const float* pv = (const float*)d_in[2];
    const int*   am = (const int*)  d_in[3];
    const float* Wq = (const float*)d_in[4];
    const float* bq = (const float*)d_in[5];
    const float* Wk = (const float*)d_in[6];
    const float* bk = (const float*)d_in[7];
    const float* Wv = (const float*)d_in[8];
    const float* bv = (const float*)d_in[9];
    const float* Wo = (const float*)d_in[10];
    const float* bo = (const float*)d_in[11];
    float* out = (float*)d_out;

    uint2 *hs_s, *wq_s, *wk_s, *wv_s, *wo_s, *qs, *kcs, *as;
    float *klin, *vlin, *vc, *sc;
    cudaGetSymbolAddress((void**)&hs_s, g_hs_s);
    cudaGetSymbolAddress((void**)&wq_s, g_wq_s);
    cudaGetSymbolAddress((void**)&wk_s, g_wk_s);
    cudaGetSymbolAddress((void**)&wv_s, g_wv_s);
    cudaGetSymbolAddress((void**)&wo_s, g_wo_s);
    cudaGetSymbolAddress((void**)&qs,   g_qs);
    cudaGetSymbolAddress((void**)&kcs,  g_kcs);
    cudaGetSymbolAddress((void**)&as,   g_as);
    cudaGetSymbolAddress((void**)&klin, g_klin);
    cudaGetSymbolAddress((void**)&vlin, g_vlin);
    cudaGetSymbolAddress((void**)&vc,   g_vc);
    cudaGetSymbolAddress((void**)&sc,   g_scores);

    const size_t n4_hs = (size_t)TOKS*HID/4;
    const size_t n4_wq = (size_t)HID*HID/4;
    const size_t n4_wk = (size_t)NKV*HD*HID/4;
    split_f32<<<(unsigned)((n4_hs+255)/256), 256>>>(hs, hs_s, n4_hs);
    split_f32<<<(unsigned)((n4_wq+255)/256), 256>>>(Wq, wq_s, n4_wq);
    split_f32<<<(unsigned)((n4_wk+255)/256), 256>>>(Wk, wk_s, n4_wk);
    split_f32<<<(unsigned)((n4_wk+255)/256), 256>>>(Wv, wv_s, n4_wk);
    split_f32<<<(unsigned)((n4_wq+255)/256), 256>>>(Wo, wo_s, n4_wq);

    gemm_s<true ><<<dim3(HID/128, TOKS/128), 256>>>(hs_s, wq_s, bq, qs, HID, HID);
    gemm_s<false><<<dim3((NKV*HD)/128, TOKS/128), 256>>>(hs_s, wk_s, bk, klin, NKV*HD, HID);
    gemm_s<false><<<dim3((NKV*HD)/128, TOKS/128), 256>>>(hs_s, wv_s, bv, vlin, NKV*HD, HID);

    pack_kv_s<<<(BATCH*NKV*KVLEN*32)/256, 256>>>(pk, pv, klin, vlin, kcs, vc);

    qk_gemm_s<<<dim3(KVLEN/128, SQ/128, BATCH*NH), 256>>>(qs, kcs, am, sc);
    softmax_rows_s<<<BATCH*NH*SQ, 256>>>(sc);
    pv_gemm_s<<<dim3(1, SQ/128, BATCH*NH), 256>>>((const uint2*)sc, vc, as);

    gemm_s<false><<<dim3(HID/128, TOKS/128), 256>>>(as, wo_s, bo, out, HID, HID);
}

// round 16
// speedup vs baseline: 2.3703x; 1.0321x over previous
#include <cuda_runtime.h>
#include <cuda_fp16.h>
#include <cstdint>

#define BATCH 4
#define SQ    1024
#define HID   4096
#define NH    32
#define NKV   8
#define HD    128
#define KVLEN 2048
#define TOKS  (BATCH*SQ)

// ---------------- scratch (device globals; allocation-free) ----------------
// packed split format: uint2 { fp16x2 hi(k,k+1), fp16x2 lo(k,k+1) } per k-pair
__device__ uint2 g_hs_s[(size_t)TOKS*HID/2];
__device__ uint2 g_wq_s[(size_t)HID*HID/2];
__device__ uint2 g_wk_s[(size_t)NKV*HD*HID/2];
__device__ uint2 g_wv_s[(size_t)NKV*HD*HID/2];
__device__ uint2 g_wo_s[(size_t)HID*HID/2];
__device__ uint2 g_qs [(size_t)TOKS*HID/2];
__device__ float g_klin[(size_t)TOKS*NKV*HD];
__device__ float g_vlin[(size_t)TOKS*NKV*HD];
__device__ uint2 g_kcs[(size_t)BATCH*NKV*KVLEN*HD/2];
__device__ float g_vc [(size_t)BATCH*NKV*KVLEN*HD];
__device__ uint2 g_as [(size_t)TOKS*HID/2];
__device__ float g_scores[(size_t)BATCH*NH*SQ*KVLEN];

// ---------------- fp16 split helpers ----------------
__device__ __forceinline__ uint32_t hpack(__half a, __half b) {
    uint16_t ua = *reinterpret_cast<uint16_t*>(&a);
    uint16_t ub = *reinterpret_cast<uint16_t*>(&b);
    return (uint32_t)ua | ((uint32_t)ub << 16);
}

__device__ __forceinline__ uint2 splitpair(float x0, float x1) {
    __half h0 = __float2half_rn(x0);
    __half h1 = __float2half_rn(x1);
    __half l0 = __float2half_rn(x0 - __half2float(h0));
    __half l1 = __float2half_rn(x1 - __half2float(h1));
    uint2 o; o.x = hpack(h0, h1); o.y = hpack(l0, l1);
    return o;
}

__device__ __forceinline__ uint4 split4(float4 v) {
    uint2 p0 = splitpair(v.x, v.y);
    uint2 p1 = splitpair(v.z, v.w);
    return make_uint4(p0.x, p0.y, p1.x, p1.y);
}

__device__ __forceinline__ void mma16(float* d,
                                      uint32_t a0, uint32_t a1, uint32_t a2, uint32_t a3,
                                      uint32_t b0, uint32_t b1) {
    asm volatile(
        "mma.sync.aligned.m16n8k16.row.col.f32.f16.f16.f32 "
        "{%0,%1,%2,%3}, {%4,%5,%6,%7}, {%8,%9}, {%0,%1,%2,%3};\n"
        : "+f"(d[0]), "+f"(d[1]), "+f"(d[2]), "+f"(d[3])
        : "r"(a0), "r"(a1), "r"(a2), "r"(a3), "r"(b0), "r"(b1));
}

// ---------------------------------------------------------------------------
// Tile: 128 rows x 32 k = 16 k-pairs/row -> smem uint2[128][20] (pad 4).
// ---------------------------------------------------------------------------
#define TSTRIDE 20

__device__ __forceinline__ void load_tile_u(const uint2* __restrict__ g, size_t ld,
                                            int tid, uint4 f[4]) {
    const int row = tid >> 3, c = (tid & 7) * 2;
#pragma unroll
    for (int j = 0; j < 4; ++j)
        f[j] = *reinterpret_cast<const uint4*>(g + (size_t)(row + 32*j)*ld + c);
}

__device__ __forceinline__ void store_tile_u(uint2* __restrict__ S, int tid,
                                             const uint4 f[4]) {
    const int row = tid >> 3, c = (tid & 7) * 2;
#pragma unroll
    for (int j = 0; j < 4; ++j)
        *reinterpret_cast<uint4*>(&S[(row + 32*j)*TSTRIDE + c]) = f[j];
}

// 128x128x32 block compute: warp grid 2(m) x 4(n), warp tile 64x32, mma 4x4.
// NPASS=2: Ah*Bh + Al*Bh  (= A . fp16(B));  NPASS=1: Ah*Bh  (fp16(A).fp16(B))
template<int NPASS>
__device__ __forceinline__ void mma_block(const uint2* __restrict__ As,
                                          const uint2* __restrict__ Bs,
                                          int wm, int wn, int g, int t,
                                          float acc[4][4][4])
{
#pragma unroll
    for (int s = 0; s < 2; ++s) {
        uint2 af[4][4];
#pragma unroll
        for (int mt = 0; mt < 4; ++mt) {
            const int r0 = (wm + mt*16 + g)*TSTRIDE + s*8 + t;
            af[mt][0] = As[r0];
            af[mt][1] = As[r0 + 8*TSTRIDE];
            af[mt][2] = As[r0 + 4];
            af[mt][3] = As[r0 + 8*TSTRIDE + 4];
        }
        uint32_t bf[4][2];
#pragma unroll
        for (int nt = 0; nt < 4; ++nt) {
            const int rb = (wn + nt*8 + g)*TSTRIDE + s*8 + t;
            bf[nt][0] = Bs[rb].x;
            bf[nt][1] = Bs[rb + 4].x;
        }
#pragma unroll
        for (int mt = 0; mt < 4; ++mt)
#pragma unroll
            for (int nt = 0; nt < 4; ++nt) {
                mma16(acc[mt][nt], af[mt][0].x, af[mt][1].x, af[mt][2].x, af[mt][3].x,
                      bf[nt][0], bf[nt][1]);
                if (NPASS == 2)
                    mma16(acc[mt][nt], af[mt][0].y, af[mt][1].y, af[mt][2].y, af[mt][3].y,
                          bf[nt][0], bf[nt][1]);
            }
    }
}

// ---------------------------------------------------------------------------
// GEMM on pre-split operands: C[M,N] = A[M,K].B[N,K]^T + bias.
// ---------------------------------------------------------------------------
template<int NPASS, bool SPLIT_OUT>
__global__ __launch_bounds__(256)
void gemm_s(const uint2* __restrict__ A, const uint2* __restrict__ B,
            const float* __restrict__ bias, void* __restrict__ Cv,
            int N, int K)
{
    __shared__ uint2 As[128*TSTRIDE], Bs[128*TSTRIDE];
    const int tid = threadIdx.x;
    const int warp = tid >> 5, lane = tid & 31, g = lane >> 2, t = lane & 3;
    const int wm = (warp >> 2)*64, wn = (warp & 3)*32;
    const size_t m0 = (size_t)blockIdx.y*128, n0 = (size_t)blockIdx.x*128;
    const size_t lda = (size_t)K >> 1;
    const uint2* Ag = A + m0*lda;
    const uint2* Bg = B + n0*lda;

    float acc[4][4][4] = {};
    uint4 fa[4], fb[4];
    const int KT = K >> 5;

    load_tile_u(Ag, lda, tid, fa);
    load_tile_u(Bg, lda, tid, fb);

    for (int kt = 0; kt < KT; ++kt) {
        store_tile_u(As, tid, fa);
        store_tile_u(Bs, tid, fb);
        __syncthreads();
        if (kt + 1 < KT) {
            load_tile_u(Ag + (size_t)(kt+1)*16, lda, tid, fa);
            load_tile_u(Bg + (size_t)(kt+1)*16, lda, tid, fb);
        }
        mma_block<NPASS>(As, Bs, wm, wn, g, t, acc);
        __syncthreads();
    }

#pragma unroll
    for (int mt = 0; mt < 4; ++mt) {
        const size_t r0 = m0 + wm + mt*16 + g, r1 = r0 + 8;
#pragma unroll
        for (int nt = 0; nt < 4; ++nt) {
            const int col = (int)n0 + wn + nt*8 + t*2;
            const float b0 = bias[col], b1 = bias[col+1];
            if (SPLIT_OUT) {
                uint2* C = reinterpret_cast<uint2*>(Cv);
                const size_t ldc = (size_t)N >> 1;
                C[r0*ldc + (col>>1)] = splitpair(acc[mt][nt][0]+b0, acc[mt][nt][1]+b1);
                C[r1*ldc + (col>>1)] = splitpair(acc[mt][nt][2]+b0, acc[mt][nt][3]+b1);
            } else {
                float* C = reinterpret_cast<float*>(Cv);
                C[r0*N + col]   = acc[mt][nt][0] + b0;
                C[r0*N + col+1] = acc[mt][nt][1] + b1;
                C[r1*N + col]   = acc[mt][nt][2] + b0;
                C[r1*N + col+1] = acc[mt][nt][3] + b1;
            }
        }
    }
}

// ---------------------------------------------------------------------------
// Pre-split kernel: f32 array -> packed split uint2 (same byte size).
// ---------------------------------------------------------------------------
__global__ __launch_bounds__(256)
void split_f32(const float* __restrict__ in, uint2* __restrict__ out, size_t n4)
{
    const size_t i = (size_t)blockIdx.x*256 + threadIdx.x;
    if (i >= n4) return;
    float4 v = reinterpret_cast<const float4*>(in)[i];
    reinterpret_cast<uint4*>(out)[i] = split4(v);
}

// ---------------------------------------------------------------------------
// KV cache concat pack: K cache -> split uint2, V cache -> f32.
// ---------------------------------------------------------------------------
__global__ __launch_bounds__(256)
void pack_kv_s(const float* __restrict__ pk, const float* __restrict__ pv,
               const float* __restrict__ kl, const float* __restrict__ vl,
               uint2* __restrict__ kcs, float* __restrict__ vc)
{
    const size_t idx = (size_t)blockIdx.x*256 + threadIdx.x;
    const int d4 = (int)(idx & 31);
    const int s  = (int)((idx >> 5) & 2047);
    const int hh = (int)((idx >> 16) & 7);
    const int bb = (int)(idx >> 19);
    float4 kv, vv;
    if (s < 1024) {
        const size_t src = (((size_t)bb*NKV + hh)*1024 + s)*HD + d4*4;
        kv = *reinterpret_cast<const float4*>(pk + src);
        vv = *reinterpret_cast<const float4*>(pv + src);
    } else {
        const size_t src = ((size_t)bb*SQ + (s - 1024))*(NKV*HD) + hh*HD + d4*4;
        kv = *reinterpret_cast<const float4*>(kl + src);
        vv = *reinterpret_cast<const float4*>(vl + src);
    }
    const size_t row = ((size_t)bb*NKV + hh)*KVLEN + s;
    *reinterpret_cast<uint4*>(kcs + row*(HD/2) + d4*2) = split4(kv);
    *reinterpret_cast<float4*>(vc + row*HD + d4*4) = vv;
}

// ---------------------------------------------------------------------------
// Batched QK^T on pre-split Q and K-cache. grid (KVLEN/128, SQ/128, B*NH)
// ---------------------------------------------------------------------------
__global__ __launch_bounds__(256)
void qk_gemm_s(const uint2* __restrict__ Q, const uint2* __restrict__ Kcs,
               const int* __restrict__ amask, float* __restrict__ S)
{
    __shared__ uint2 As[128*TSTRIDE], Bs[128*TSTRIDE];
    const int tid = threadIdx.x;
    const int warp = tid >> 5, lane = tid & 31, g = lane >> 2, t = lane & 3;
    const int wm = (warp >> 2)*64, wn = (warp & 3)*32;
    const int z = blockIdx.z, b = z >> 5, h = z & 31;
    const size_t m0 = (size_t)blockIdx.y*128, n0 = (size_t)blockIdx.x*128;
    const uint2* Ag = Q + ((size_t)b*SQ + m0)*(HID/2) + h*(HD/2);
    const uint2* Bg = Kcs + (((size_t)b*NKV + (h >> 2))*KVLEN + n0)*(HD/2);
    const float scale = 0.08838834764831843f;   // 1/sqrt(128)

    float acc[4][4][4] = {};
    uint4 fa[4], fb[4];

    load_tile_u(Ag, HID/2, tid, fa);
    load_tile_u(Bg, HD/2, tid, fb);

    for (int kt = 0; kt < 4; ++kt) {            // K = 128
        store_tile_u(As, tid, fa);
        store_tile_u(Bs, tid, fb);
        __syncthreads();
        if (kt + 1 < 4) {
            load_tile_u(Ag + (size_t)(kt+1)*16, HID/2, tid, fa);
            load_tile_u(Bg + (size_t)(kt+1)*16, HD/2, tid, fb);
        }
        mma_block<2>(As, Bs, wm, wn, g, t, acc);
        __syncthreads();
    }

    float* Sb = S + (size_t)z*SQ*KVLEN;
#pragma unroll
    for (int mt = 0; mt < 4; ++mt) {
        const size_t r0 = m0 + wm + mt*16 + g, r1 = r0 + 8;
#pragma unroll
        for (int nt = 0; nt < 4; ++nt) {
            const int col = (int)n0 + wn + nt*8 + t*2;
            const bool mk0 = amask[(size_t)b*KVLEN + col] != 0;
            const bool mk1 = amask[(size_t)b*KVLEN + col + 1] != 0;
            Sb[r0*KVLEN + col]   = mk0 ? -1e9f : acc[mt][nt][0]*scale;
            Sb[r0*KVLEN + col+1] = mk1 ? -1e9f : acc[mt][nt][1]*scale;
            Sb[r1*KVLEN + col]   = mk0 ? -1e9f : acc[mt][nt][2]*scale;
            Sb[r1*KVLEN + col+1] = mk1 ? -1e9f : acc[mt][nt][3]*scale;
        }
    }
}

// ---------------------------------------------------------------------------
// Row softmax over KVLEN=2048, writes packed split IN PLACE (same bytes).
// grid = B*NH*SQ, 256 threads.
// ---------------------------------------------------------------------------
__global__ __launch_bounds__(256)
void softmax_rows_s(float* __restrict__ S)
{
    float* p = S + (size_t)blockIdx.x*KVLEN;
    const int tid = threadIdx.x;
    float4 a = *reinterpret_cast<float4*>(p + tid*4);
    float4 c = *reinterpret_cast<float4*>(p + 1024 + tid*4);
    float x[8] = {a.x, a.y, a.z, a.w, c.x, c.y, c.z, c.w};

    float m = x[0];
#pragma unroll
    for (int i = 1; i < 8; ++i) m = fmaxf(m, x[i]);
#pragma unroll
    for (int o = 16; o; o >>= 1) m = fmaxf(m, __shfl_xor_sync(0xffffffffu, m, o));
    __shared__ float red[8];
    if ((tid & 31) == 0) red[tid >> 5] = m;
    __syncthreads();
    float M = red[0];
#pragma unroll
    for (int i = 1; i < 8; ++i) M = fmaxf(M, red[i]);
    __syncthreads();

    float s = 0.f;
#pragma unroll
    for (int i = 0; i < 8; ++i) { x[i] = __expf(x[i] - M); s += x[i]; }
#pragma unroll
    for (int o = 16; o; o >>= 1) s += __shfl_xor_sync(0xffffffffu, s, o);
    if ((tid & 31) == 0) red[tid >> 5] = s;
    __syncthreads();
    float T = 0.f;
#pragma unroll
    for (int i = 0; i < 8; ++i) T += red[i];
    const float r = 1.f / T;

    uint2* ps = reinterpret_cast<uint2*>(p);
    *reinterpret_cast<uint4*>(&ps[tid*2]) =
        split4(make_float4(x[0]*r, x[1]*r, x[2]*r, x[3]*r));
    *reinterpret_cast<uint4*>(&ps[512 + tid*2]) =
        split4(make_float4(x[4]*r, x[5]*r, x[6]*r, x[7]*r));
}

// ---------------------------------------------------------------------------
// Batched PV on pre-split P (1-pass: fp16(P).fp16(V)); V transposed+split
// while staging. Writes attn split. grid (1, SQ/128, B*NH)
// ---------------------------------------------------------------------------
__global__ __launch_bounds__(256)
void pv_gemm_s(const uint2* __restrict__ P, const float* __restrict__ V,
               uint2* __restrict__ O)
{
    __shared__ uint2 As[128*TSTRIDE], Bs[128*TSTRIDE];
    const int tid = threadIdx.x;
    const int warp = tid >> 5, lane = tid & 31, g = lane >> 2, t = lane & 3;
    const int wm = (warp >> 2)*64, wn = (warp & 3)*32;
    const int z = blockIdx.z, b = z >> 5, h = z & 31;
    const size_t m0 = (size_t)blockIdx.y*128;
    const uint2* Ag = P + ((size_t)z*SQ + m0)*(KVLEN/2);
    const float* Vg = V + ((size_t)b*NKV + (h >> 2))*KVLEN*HD;

    const int kp = tid & 15, nh0 = tid >> 4;   // V transpose mapping

    float acc[4][4][4] = {};
    uint4 fa[4];
    float4 fv[2][2];

    auto load_v = [&](int kt) {
        const float* Vt = Vg + (size_t)kt*32*HD;
#pragma unroll
        for (int j = 0; j < 2; ++j) {
            const int nq = nh0 + 16*j;
            fv[j][0] = *reinterpret_cast<const float4*>(Vt + (size_t)(2*kp)*HD + nq*4);
            fv[j][1] = *reinterpret_cast<const float4*>(Vt + (size_t)(2*kp+1)*HD + nq*4);
        }
    };
    auto store_v = [&]() {
#pragma unroll
        for (int j = 0; j < 2; ++j) {
            const int n0 = (nh0 + 16*j)*4;
            Bs[(n0+0)*TSTRIDE + kp] = splitpair(fv[j][0].x, fv[j][1].x);
            Bs[(n0+1)*TSTRIDE + kp] = splitpair(fv[j][0].y, fv[j][1].y);
            Bs[(n0+2)*TSTRIDE + kp] = splitpair(fv[j][0].z, fv[j][1].z);
            Bs[(n0+3)*TSTRIDE + kp] = splitpair(fv[j][0].w, fv[j][1].w);
        }
    };

    load_tile_u(Ag, KVLEN/2, tid, fa);
    load_v(0);

    for (int kt = 0; kt < KVLEN/32; ++kt) {
        store_tile_u(As, tid, fa);
        store_v();
        __syncthreads();
        if (kt + 1 < KVLEN/32) {
            load_tile_u(Ag + (size_t)(kt+1)*16, KVLEN/2, tid, fa);
            load_v(kt + 1);
        }
        mma_block<1>(As, Bs, wm, wn, g, t, acc);
        __syncthreads();
    }

#pragma unroll
    for (int mt = 0; mt < 4; ++mt) {
        const size_t r0 = (size_t)b*SQ + m0 + wm + mt*16 + g, r1 = r0 + 8;
#pragma unroll
        for (int nt = 0; nt < 4; ++nt) {
            const int col = h*HD + wn + nt*8 + t*2;
            O[r0*(HID/2) + (col>>1)] = splitpair(acc[mt][nt][0], acc[mt][nt][1]);
            O[r1*(HID/2) + (col>>1)] = splitpair(acc[mt][nt][2], acc[mt][nt][3]);
        }
    }
}

// ---------------------------------------------------------------------------
extern "C" void kernel_launch(void* const* d_in, const int* in_sizes, int n_in,
                              void* d_out, int out_size)
{
    (void)in_sizes; (void)n_in; (void)out_size;
    const float* hs = (const float*)d_in[0];
    const float* pk = (const float*)d_in[1];
    const float* pv = (const float*)d_in[2];
    const int*   am = (const int*)  d_in[3];
    const float* Wq = (const float*)d_in[4];
    const float* bq = (const float*)d_in[5];
    const float* Wk = (const float*)d_in[6];
    const float* bk = (const float*)d_in[7];
    const float* Wv = (const float*)d_in[8];
    const float* bv = (const float*)d_in[9];
    const float* Wo = (const float*)d_in[10];
    const float* bo = (const float*)d_in[11];
    float* out = (float*)d_out;

    uint2 *hs_s, *wq_s, *wk_s, *wv_s, *wo_s, *qs, *kcs, *as;
    float *klin, *vlin, *vc, *sc;
    cudaGetSymbolAddress((void**)&hs_s, g_hs_s);
    cudaGetSymbolAddress((void**)&wq_s, g_wq_s);
    cudaGetSymbolAddress((void**)&wk_s, g_wk_s);
    cudaGetSymbolAddress((void**)&wv_s, g_wv_s);
    cudaGetSymbolAddress((void**)&wo_s, g_wo_s);
    cudaGetSymbolAddress((void**)&qs,   g_qs);
    cudaGetSymbolAddress((void**)&kcs,  g_kcs);
    cudaGetSymbolAddress((void**)&as,   g_as);
    cudaGetSymbolAddress((void**)&klin, g_klin);
    cudaGetSymbolAddress((void**)&vlin, g_vlin);
    cudaGetSymbolAddress((void**)&vc,   g_vc);
    cudaGetSymbolAddress((void**)&sc,   g_scores);

    const size_t n4_hs = (size_t)TOKS*HID/4;
    const size_t n4_wq = (size_t)HID*HID/4;
    const size_t n4_wk = (size_t)NKV*HD*HID/4;
    split_f32<<<(unsigned)((n4_hs+255)/256), 256>>>(hs, hs_s, n4_hs);
    split_f32<<<(unsigned)((n4_wq+255)/256), 256>>>(Wq, wq_s, n4_wq);
    split_f32<<<(unsigned)((n4_wk+255)/256), 256>>>(Wk, wk_s, n4_wk);
    split_f32<<<(unsigned)((n4_wk+255)/256), 256>>>(Wv, wv_s, n4_wk);
    split_f32<<<(unsigned)((n4_wq+255)/256), 256>>>(Wo, wo_s, n4_wq);

    gemm_s<2, true ><<<dim3(HID/128, TOKS/128), 256>>>(hs_s, wq_s, bq, qs, HID, HID);
    gemm_s<2, false><<<dim3((NKV*HD)/128, TOKS/128), 256>>>(hs_s, wk_s, bk, klin, NKV*HD, HID);
    gemm_s<2, false><<<dim3((NKV*HD)/128, TOKS/128), 256>>>(hs_s, wv_s, bv, vlin, NKV*HD, HID);

    pack_kv_s<<<(BATCH*NKV*KVLEN*32)/256, 256>>>(pk, pv, klin, vlin, kcs, vc);

    qk_gemm_s<<<dim3(KVLEN/128, SQ/128, BATCH*NH), 256>>>(qs, kcs, am, sc);
    softmax_rows_s<<<BATCH*NH*SQ, 256>>>(sc);
    pv_gemm_s<<<dim3(1, SQ/128, BATCH*NH), 256>>>((const uint2*)sc, vc, as);

    gemm_s<1, false><<<dim3(HID/128, TOKS/128), 256>>>(as, wo_s, bo, out, HID, HID);
}